// round 9
// baseline (speedup 1.0000x reference)
#include <cuda_runtime.h>
#include <cuda_bf16.h>
#include <cstdint>

#define B_   32
#define D_   256
#define HW_  1024
#define N_   32768
#define K_   1024
#define MARGIN 1e-3f
#define FINF 3.4e38f

static const long long Q_OFF = 8388608LL;   // B*D*H*W

// ---------------- device globals ----------------
__device__ int    g_idx[N_];
__device__ float  g_c2[K_];
__device__ float  g_x2[N_];
__device__ double g_acc;
__device__ __align__(16) float         g_xt[(size_t)N_ * D_];
__device__ __align__(16) __nv_bfloat16 g_xh[(size_t)N_ * D_];
__device__ __align__(16) __nv_bfloat16 g_ch[(size_t)K_ * D_];
__device__ float g_cv[N_][4];
__device__ int   g_ci[N_][4];
__device__ int   g_qa[N_];
__device__ int   g_qb[N_];
__device__ int   g_qa_n;
__device__ int   g_qb_n;

__device__ __forceinline__ uint32_t smem_u32(const void* p) {
    uint32_t a;
    asm("{ .reg .u64 t; cvta.to.shared.u64 t, %1; cvt.u32.u64 %0, t; }"
        : "=r"(a) : "l"(p));
    return a;
}
#define LDSM_X4(r0, r1, r2, r3, addr) \
    asm volatile("ldmatrix.sync.aligned.m8n8.x4.shared.b16 {%0,%1,%2,%3}, [%4];" \
                 : "=r"(r0), "=r"(r1), "=r"(r2), "=r"(r3) : "r"(addr))
#define MMA_BF16(c, a0, a1, a2, a3, b0, b1) \
    asm volatile("mma.sync.aligned.m16n8k16.row.col.f32.bf16.bf16.f32 " \
                 "{%0,%1,%2,%3}, {%4,%5,%6,%7}, {%8,%9}, {%0,%1,%2,%3};" \
                 : "+f"((c)[0]), "+f"((c)[1]), "+f"((c)[2]), "+f"((c)[3]) \
                 : "r"(a0), "r"(a1), "r"(a2), "r"(a3), "r"(b0), "r"(b1))
#define CP_ASYNC16(dst, src) \
    asm volatile("cp.async.cg.shared.global [%0], [%1], 16;" \
                 :: "r"(dst), "l"(src))
#define CP_COMMIT() asm volatile("cp.async.commit_group;" ::: "memory")
#define CP_WAIT(n)  asm volatile("cp.async.wait_group %0;" :: "n"(n) : "memory")

__device__ __forceinline__ void fold4(float* v, int* ix, float nv, int nk) {
    if (nv < v[3]) {
        if (nv < v[2]) {
            v[3] = v[2]; ix[3] = ix[2];
            if (nv < v[1]) {
                v[2] = v[1]; ix[2] = ix[1];
                if (nv < v[0]) { v[1] = v[0]; ix[1] = ix[0]; v[0] = nv; ix[0] = nk; }
                else           { v[1] = nv; ix[1] = nk; }
            } else { v[2] = nv; ix[2] = nk; }
        } else { v[3] = nv; ix[3] = nk; }
    }
}

// ---------------------------------------------------------------------------
__global__ void zero_kernel() { g_acc = 0.0; g_qa_n = 0; g_qb_n = 0; }

// ---------------------------------------------------------------------------
// prep_cb: bf16 hi split; exact c2 (sequential no-FMA).
// ---------------------------------------------------------------------------
__global__ __launch_bounds__(256) void prep_cb(const float* __restrict__ cb) {
    __shared__ float row[256];
    const int k = blockIdx.x, t = threadIdx.x;
    const float v = cb[(size_t)k * D_ + t];
    row[t] = v;
    g_ch[(size_t)k * D_ + t] = __float2bfloat16(v);
    __syncthreads();
    if (t == 0) {
        float s = 0.f;
        for (int d = 0; d < D_; ++d)
            s = __fadd_rn(s, __fmul_rn(row[d], row[d]));
        g_c2[k] = s;
    }
}

// ---------------------------------------------------------------------------
// prep_x: transpose (B,D,H,W)->(N,D), exact x2, fp32 copy + bf16 hi split.
// ---------------------------------------------------------------------------
__global__ __launch_bounds__(256) void prep_x(const float* __restrict__ x) {
    extern __shared__ float xs[];   // [64][257]
    const int t   = threadIdx.x;
    const int n0  = blockIdx.x * 64;
    const int b   = n0 >> 10;
    const int hw0 = n0 & 1023;
    const float* xb = x + ((size_t)b << 18) + hw0;

#pragma unroll 8
    for (int i = 0; i < 64; ++i) {
        const int e = t + (i << 8);
        const int d = e >> 6, n = e & 63;
        xs[n * 257 + d] = xb[((size_t)d << 10) + n];
    }
    __syncthreads();

    if (t < 64) {
        const float* r = xs + t * 257;
        float s = 0.f;
        for (int d = 0; d < D_; ++d)
            s = __fadd_rn(s, __fmul_rn(r[d], r[d]));
        g_x2[n0 + t] = s;
    }

#pragma unroll 8
    for (int i = 0; i < 64; ++i) {
        const int e = t + (i << 8);
        const int n = e >> 8, d = e & 255;
        const float v = xs[n * 257 + d];
        const size_t gi = ((size_t)(n0 + n) << 8) + d;
        g_xt[gi] = v;
        g_xh[gi] = __float2bfloat16(v);
    }
}

// ---------------------------------------------------------------------------
// gemm_argmin: single-pass HMMA GEMM  s = xh*ch  (error sigma ~2.8e-5 <<
// MARGIN; exact refine repairs all in-margin rows). 64-row CTAs, 2 CTAs/SM.
// B hi 64-code chunks, cp.async double-buffered. Fused top-4 epilogue with
// shuffle q-merge.
// ---------------------------------------------------------------------------
#define PITCH 264
#define SA        0
#define SA_BYTES  (64 * PITCH * 2)               // 33792
#define SB        SA_BYTES                       // 33792
#define SB_STRIDE (64 * PITCH * 2)               // 33792 per buffer
#define S_C2      (SB + 2 * SB_STRIDE)           // 101376
#define S_X2      (S_C2 + 4096)                  // 105472
#define S_MGV     (S_X2 + 256)                   // 105728 (64*2*4 floats)
#define S_MGI     (S_MGV + 2048)                 // 107776 (64*2*4 ints)
#define GEMM_SMEM (S_MGI + 2048)                 // 109824

__device__ __forceinline__ void stage_b(uint32_t sb, int buf, int kc, int t) {
    const uint32_t dst = sb + SB + buf * SB_STRIDE;
#pragma unroll
    for (int i = 0; i < 8; ++i) {
        const int e = t + (i << 8);               // 0..2047
        const int row = e >> 5;                   // 0..63
        const int c8 = (e & 31) << 3;             // 0..248
        CP_ASYNC16(dst + (uint32_t)(row * PITCH + c8) * 2,
                   g_ch + (((size_t)((kc << 6) + row)) << 8) + c8);
    }
}

__global__ __launch_bounds__(256, 2) void gemm_argmin() {
    extern __shared__ char sm[];
    __nv_bfloat16* Ah = (__nv_bfloat16*)(sm + SA);
    float* c2s = (float*)(sm + S_C2);
    float* x2s = (float*)(sm + S_X2);
    float* mgv = (float*)(sm + S_MGV);
    int*   mgi = (int*)(sm + S_MGI);

    const int t    = threadIdx.x;
    const int lane = t & 31;
    const int w    = t >> 5;
    const int wm   = (w >> 1) << 4;               // M-tile base row (0,16,32,48)
    const int wn   = (w & 1);                     // N half of chunk
    const int g = lane >> 2, q = lane & 3;
    const int n0 = blockIdx.x * 64;
    const uint32_t sb = smem_u32(sm);

    // kick off B chunk 0 (overlaps A-resident loads)
    stage_b(sb, 0, 0, t);
    CP_COMMIT();

    // resident A (hi), c2, x2
#pragma unroll
    for (int i = 0; i < 8; ++i) {
        const int e = t + (i << 8);
        const int row = e >> 5, c8 = (e & 31) << 3;
        *(uint4*)(Ah + row * PITCH + c8) =
            *(const uint4*)(g_xh + ((size_t)(n0 + row) << 8) + c8);
    }
#pragma unroll
    for (int i = 0; i < 4; ++i) c2s[t + (i << 8)] = g_c2[t + (i << 8)];
    if (t < 64) x2s[t] = g_x2[n0 + t];

    const uint32_t a_idx = (uint32_t)((wm + (lane & 15)) * PITCH + ((lane >> 4) << 3));
    const uint32_t aoh = sb + SA + a_idx * 2;
    const uint32_t b_idx = (uint32_t)(((lane & 7) + ((lane >> 4) << 3)) * PITCH
                                      + (((lane >> 3) & 1) << 3));
    const uint32_t bgrp = (uint32_t)((wn << 5) * PITCH) * 2;   // N-half offset

    float tv[2][4];
    int   ti[2][4];
#pragma unroll
    for (int r = 0; r < 2; ++r)
#pragma unroll
        for (int s = 0; s < 4; ++s) { tv[r][s] = FINF; ti[r][s] = 0; }

    for (int nc = 0; nc < 16; ++nc) {
        const int buf = nc & 1;
        if (nc < 15) { stage_b(sb, buf ^ 1, nc + 1, t); CP_COMMIT(); CP_WAIT(1); }
        else         { CP_WAIT(0); }
        __syncthreads();

        const uint32_t bh = sb + SB + buf * SB_STRIDE + bgrp + b_idx * 2;

        float acc[4][4];
#pragma unroll
        for (int j = 0; j < 4; ++j)
#pragma unroll
            for (int s = 0; s < 4; ++s) acc[j][s] = 0.f;

#pragma unroll 4
        for (int k = 0; k < 16; ++k) {
            uint32_t a0, a1, a2, a3;
            uint32_t b00, b01, b02, b03, b10, b11, b12, b13;
            LDSM_X4(a0, a1, a2, a3, aoh + k * 32);
            LDSM_X4(b00, b01, b02, b03, bh + k * 32);
            LDSM_X4(b10, b11, b12, b13, bh + 16 * PITCH * 2 + k * 32);
            MMA_BF16(acc[0], a0, a1, a2, a3, b00, b01);
            MMA_BF16(acc[1], a0, a1, a2, a3, b02, b03);
            MMA_BF16(acc[2], a0, a1, a2, a3, b10, b11);
            MMA_BF16(acc[3], a0, a1, a2, a3, b12, b13);
        }

        // epilogue: fold this warp's 32 columns into per-thread top-4
        const float x2lo = x2s[wm + g];
        const float x2hi = x2s[wm + 8 + g];
#pragma unroll
        for (int j = 0; j < 4; ++j) {
            const int colb = (nc << 6) + (wn << 5) + (j << 3) + (q << 1);
            const float c2a = c2s[colb], c2b = c2s[colb + 1];
            fold4(tv[0], ti[0], __fadd_rn(__fadd_rn(x2lo, -2.f * acc[j][0]), c2a), colb);
            fold4(tv[0], ti[0], __fadd_rn(__fadd_rn(x2lo, -2.f * acc[j][1]), c2b), colb + 1);
            fold4(tv[1], ti[1], __fadd_rn(__fadd_rn(x2hi, -2.f * acc[j][2]), c2a), colb);
            fold4(tv[1], ti[1], __fadd_rn(__fadd_rn(x2hi, -2.f * acc[j][3]), c2b), colb + 1);
        }
        __syncthreads();
    }

    // merge across the 4 q-lanes via shuffles (lanes 4g..4g+3 share rows)
#pragma unroll
    for (int r = 0; r < 2; ++r) {
#pragma unroll
        for (int m = 1; m <= 2; m <<= 1) {
            float ov[4]; int oi[4];
#pragma unroll
            for (int s = 0; s < 4; ++s) {
                ov[s] = __shfl_xor_sync(0xffffffffu, tv[r][s], m);
                oi[s] = __shfl_xor_sync(0xffffffffu, ti[r][s], m);
            }
#pragma unroll
            for (int s = 0; s < 4; ++s) fold4(tv[r], ti[r], ov[s], oi[s]);
        }
    }
    if (q == 0) {
        const int row0 = wm + g, row1 = wm + 8 + g;
#pragma unroll
        for (int s = 0; s < 4; ++s) {
            mgv[(row0 * 2 + wn) * 4 + s] = tv[0][s];
            mgi[(row0 * 2 + wn) * 4 + s] = ti[0][s];
            mgv[(row1 * 2 + wn) * 4 + s] = tv[1][s];
            mgi[(row1 * 2 + wn) * 4 + s] = ti[1][s];
        }
    }
    __syncthreads();
    // merge the two N-half lists per row
    if (t < 64) {
        float bv[4] = {FINF, FINF, FINF, FINF};
        int   bi[4] = {0, 0, 0, 0};
#pragma unroll
        for (int h = 0; h < 2; ++h)
#pragma unroll
            for (int s = 0; s < 4; ++s)
                fold4(bv, bi, mgv[(t * 2 + h) * 4 + s], mgi[(t * 2 + h) * 4 + s]);
        const int n = n0 + t;
#pragma unroll
        for (int s = 0; s < 4; ++s) { g_cv[n][s] = bv[s]; g_ci[n][s] = bi[s]; }
    }
}

// ---------------------------------------------------------------------------
// classify: resolve unambiguous rows; compact the rest into work queues.
// ---------------------------------------------------------------------------
__global__ __launch_bounds__(256) void classify_kernel() {
    const int n = blockIdx.x * 256 + threadIdx.x;
    const float lim = g_cv[n][0] + MARGIN;
    const int ncand = 1 + (g_cv[n][1] <= lim) + (g_cv[n][2] <= lim)
                        + (g_cv[n][3] <= lim);
    if (ncand == 1) {
        g_idx[n] = g_ci[n][0];
    } else if (ncand < 4) {
        g_qa[atomicAdd(&g_qa_n, 1)] = n;
    } else {
        g_qb[atomicAdd(&g_qb_n, 1)] = n;
    }
}

// ---------------------------------------------------------------------------
// refine_small: persistent warps grid-stride over queue A (2-3 candidates).
// ---------------------------------------------------------------------------
__global__ __launch_bounds__(256) void refine_small(const float* __restrict__ cb)
{
    __shared__ float sx[8][260];
    __shared__ float sc[8][3][260];
    const int w = threadIdx.x >> 5;
    const int l = threadIdx.x & 31;
    const int wi = (blockIdx.x << 3) + w;
    const int stride = gridDim.x << 3;
    const int cnt = g_qa_n;

    for (int i = wi; i < cnt; i += stride) {
        const int n = g_qa[i];
        const float lim = g_cv[n][0] + MARGIN;
        const int ncand = 2 + (g_cv[n][2] <= lim);

        {
            const float* xr = g_xt + ((size_t)n << 8);
#pragma unroll
            for (int ii = 0; ii < 2; ++ii) {
                const int d = (l + (ii << 5)) << 2;
                *(float4*)&sx[w][d] = *(const float4*)(xr + d);
            }
        }
        for (int c = 0; c < ncand; ++c) {
            const float* cr = cb + ((size_t)g_ci[n][c] << 8);
#pragma unroll
            for (int ii = 0; ii < 2; ++ii) {
                const int d = (l + (ii << 5)) << 2;
                *(float4*)&sc[w][c][d] = *(const float4*)(cr + d);
            }
        }
        __syncwarp();

        float bestv = FINF;
        int   besti = 0x7fffffff;
        if (l < ncand) {
            const int k = g_ci[n][l];
            float s = 0.f;
#pragma unroll 16
            for (int d = 0; d < D_; ++d)
                s = fmaf(sx[w][d], sc[w][l][d], s);
            bestv = __fadd_rn(__fadd_rn(g_x2[n], -2.f * s), g_c2[k]);
            besti = k;
        }
#pragma unroll
        for (int m = 16; m; m >>= 1) {
            const float ov = __shfl_xor_sync(0xffffffffu, bestv, m);
            const int   oi = __shfl_xor_sync(0xffffffffu, besti, m);
            if (ov < bestv || (ov == bestv && oi < besti)) { bestv = ov; besti = oi; }
        }
        if (l == 0) g_idx[n] = besti;
        __syncwarp();
    }
}

// ---------------------------------------------------------------------------
// refine_full: block per saturated row; exact full scan, codebook staged
// in 64-code chunks (coalesced). dyn smem: 64*257 floats.
// ---------------------------------------------------------------------------
__global__ __launch_bounds__(256) void refine_full(const float* __restrict__ cb)
{
    extern __shared__ float scf[];          // [64][257]
    __shared__ float sxr[256];
    __shared__ float rv[256];
    __shared__ int   rk[256];
    const int t = threadIdx.x;
    const int cnt = g_qb_n;

    for (int qi = blockIdx.x; qi < cnt; qi += gridDim.x) {
        const int n = g_qb[qi];
        if (t < 64) {
            const float4 v = *(const float4*)(g_xt + ((size_t)n << 8) + (t << 2));
            sxr[(t << 2) + 0] = v.x; sxr[(t << 2) + 1] = v.y;
            sxr[(t << 2) + 2] = v.z; sxr[(t << 2) + 3] = v.w;
        }
        const float x2 = g_x2[n];
        float bestv = FINF;
        int   besti = 0x7fffffff;

        for (int base = 0; base < K_; base += 64) {
            __syncthreads();
#pragma unroll
            for (int i = 0; i < 16; ++i) {
                const int e = t + (i << 8);
                const int row = e >> 6, c4 = (e & 63) << 2;
                const float4 v = *(const float4*)(cb + ((size_t)(base + row) << 8) + c4);
                float* dst = scf + row * 257 + c4;
                dst[0] = v.x; dst[1] = v.y; dst[2] = v.z; dst[3] = v.w;
            }
            __syncthreads();
            if (t < 64) {
                const int k = base + t;
                const float* cr = scf + t * 257;
                float s = 0.f;
#pragma unroll 16
                for (int d = 0; d < D_; ++d)
                    s = fmaf(sxr[d], cr[d], s);
                const float v = __fadd_rn(__fadd_rn(x2, -2.f * s), g_c2[k]);
                if (v < bestv) { bestv = v; besti = k; }
            }
        }
        rv[t] = bestv; rk[t] = besti;
        __syncthreads();
        for (int w = 128; w > 0; w >>= 1) {
            if (t < w) {
                const float ov = rv[t + w]; const int oi = rk[t + w];
                if (ov < rv[t] || (ov == rv[t] && oi < rk[t])) { rv[t] = ov; rk[t] = oi; }
            }
            __syncthreads();
        }
        if (t == 0) g_idx[n] = rk[0];
        __syncthreads();
    }
}

// ---------------------------------------------------------------------------
// gather + straight-through output + loss partials + idx-as-float
// ---------------------------------------------------------------------------
__global__ __launch_bounds__(256) void quant_kernel(
    const float* __restrict__ x, const float* __restrict__ cb,
    float* __restrict__ out, long long out_size)
{
    __shared__ float red[256];
    const int t   = threadIdx.x;
    const int n0  = blockIdx.x * 64;
    const int b   = n0 / HW_;
    const int hw0 = n0 % HW_;
    const int tn  = t & 63;
    const int dz  = t >> 6;
    const int n   = n0 + tn;
    const int k   = g_idx[n];

    const float* xb = x   + (size_t)b * D_ * HW_ + hw0 + tn;
    float*       ob = out + (size_t)b * D_ * HW_ + hw0 + tn;
    const float* cr = cb  + (size_t)k * D_;

    float s = 0.f;
#pragma unroll 8
    for (int d = dz; d < D_; d += 4) {
        const float xv   = xb[(size_t)d * HW_];
        const float cv   = cr[d];
        const float diff = __fadd_rn(cv, -xv);
        ob[(size_t)d * HW_] = __fadd_rn(xv, diff);
        s = fmaf(diff, diff, s);
    }

    if (dz == 0 && out_size >= Q_OFF + 3 + N_)
        out[Q_OFF + 3 + n] = (float)k;

    red[t] = s;
    __syncthreads();
    for (int w = 128; w > 0; w >>= 1) {
        if (t < w) red[t] += red[t + w];
        __syncthreads();
    }
    if (t == 0) atomicAdd(&g_acc, (double)red[0]);
}

__global__ void finalize_kernel(float* __restrict__ out, long long out_size) {
    if (out_size >= Q_OFF + 3) {
        const double m = g_acc / (double)((long long)N_ * D_);
        const float  l = (float)m;
        out[Q_OFF + 0] = l;
        out[Q_OFF + 1] = l;
        out[Q_OFF + 2] = __fadd_rn(l, 0.25f * l);
    }
}

// ---------------------------------------------------------------------------
extern "C" void kernel_launch(void* const* d_in, const int* in_sizes, int n_in,
                              void* d_out, int out_size)
{
    const float* x  = (const float*)d_in[0];
    const float* cb = (const float*)d_in[1];
    float*       out = (float*)d_out;
    const long long osz = (long long)out_size;

    cudaFuncSetAttribute(prep_x,
        cudaFuncAttributeMaxDynamicSharedMemorySize, 64 * 257 * 4);
    cudaFuncSetAttribute(gemm_argmin,
        cudaFuncAttributeMaxDynamicSharedMemorySize, GEMM_SMEM);
    cudaFuncSetAttribute(refine_full,
        cudaFuncAttributeMaxDynamicSharedMemorySize, 64 * 257 * 4);

    zero_kernel<<<1, 1>>>();                       // launch 1
    prep_cb<<<K_, 256>>>(cb);                      // launch 2
    prep_x<<<512, 256, 64 * 257 * 4>>>(x);         // launch 3
    gemm_argmin<<<N_ / 64, 256, GEMM_SMEM>>>();    // launch 4 (ncu target)
    classify_kernel<<<N_ / 256, 256>>>();          // launch 5
    refine_small<<<256, 256>>>(cb);                // launch 6
    refine_full<<<64, 256, 64 * 257 * 4>>>(cb);    // launch 7
    quant_kernel<<<N_ / 64, 256>>>(x, cb, out, osz);
    finalize_kernel<<<1, 1>>>(out, osz);
}

// round 10
// speedup vs baseline: 1.5089x; 1.5089x over previous
#include <cuda_runtime.h>
#include <cuda_bf16.h>
#include <cstdint>

#define B_   32
#define D_   256
#define HW_  1024
#define N_   32768
#define K_   1024
#define MARGIN 3e-4f
#define FINF 3.4e38f

static const long long Q_OFF = 8388608LL;   // B*D*H*W

// ---------------- device globals ----------------
__device__ int    g_idx[N_];
__device__ float  g_c2[K_];
__device__ float  g_x2[N_];
__device__ double g_acc;
__device__ __align__(16) float         g_xt[(size_t)N_ * D_];
__device__ __align__(16) __nv_bfloat16 g_xh[(size_t)N_ * D_];
__device__ __align__(16) __nv_bfloat16 g_ch[(size_t)K_ * D_];
__device__ __align__(16) __nv_bfloat16 g_cl[(size_t)K_ * D_];
__device__ float g_cv[N_][4];
__device__ int   g_ci[N_][4];
__device__ int   g_qa[N_];
__device__ int   g_qb[N_];
__device__ int   g_qa_n;
__device__ int   g_qb_n;

__device__ __forceinline__ uint32_t smem_u32(const void* p) {
    uint32_t a;
    asm("{ .reg .u64 t; cvta.to.shared.u64 t, %1; cvt.u32.u64 %0, t; }"
        : "=r"(a) : "l"(p));
    return a;
}
#define LDSM_X4(r0, r1, r2, r3, addr) \
    asm volatile("ldmatrix.sync.aligned.m8n8.x4.shared.b16 {%0,%1,%2,%3}, [%4];" \
                 : "=r"(r0), "=r"(r1), "=r"(r2), "=r"(r3) : "r"(addr))
#define MMA_BF16(c, a0, a1, a2, a3, b0, b1) \
    asm volatile("mma.sync.aligned.m16n8k16.row.col.f32.bf16.bf16.f32 " \
                 "{%0,%1,%2,%3}, {%4,%5,%6,%7}, {%8,%9}, {%0,%1,%2,%3};" \
                 : "+f"((c)[0]), "+f"((c)[1]), "+f"((c)[2]), "+f"((c)[3]) \
                 : "r"(a0), "r"(a1), "r"(a2), "r"(a3), "r"(b0), "r"(b1))
#define CP_ASYNC16(dst, src) \
    asm volatile("cp.async.cg.shared.global [%0], [%1], 16;" \
                 :: "r"(dst), "l"(src))
#define CP_COMMIT() asm volatile("cp.async.commit_group;" ::: "memory")
#define CP_WAIT(n)  asm volatile("cp.async.wait_group %0;" :: "n"(n) : "memory")

__device__ __forceinline__ void fold4(float* v, int* ix, float nv, int nk) {
    if (nv < v[3]) {
        if (nv < v[2]) {
            v[3] = v[2]; ix[3] = ix[2];
            if (nv < v[1]) {
                v[2] = v[1]; ix[2] = ix[1];
                if (nv < v[0]) { v[1] = v[0]; ix[1] = ix[0]; v[0] = nv; ix[0] = nk; }
                else           { v[1] = nv; ix[1] = nk; }
            } else { v[2] = nv; ix[2] = nk; }
        } else { v[3] = nv; ix[3] = nk; }
    }
}

// ---------------------------------------------------------------------------
__global__ void zero_kernel() { g_acc = 0.0; g_qa_n = 0; g_qb_n = 0; }

// ---------------------------------------------------------------------------
// prep_cb: bf16 hi/lo split; exact c2 (sequential no-FMA).
// ---------------------------------------------------------------------------
__global__ __launch_bounds__(256) void prep_cb(const float* __restrict__ cb) {
    __shared__ float row[256];
    const int k = blockIdx.x, t = threadIdx.x;
    const float v = cb[(size_t)k * D_ + t];
    row[t] = v;
    const __nv_bfloat16 h = __float2bfloat16(v);
    const __nv_bfloat16 l = __float2bfloat16(__fsub_rn(v, __bfloat162float(h)));
    g_ch[(size_t)k * D_ + t] = h;
    g_cl[(size_t)k * D_ + t] = l;
    __syncthreads();
    if (t == 0) {
        float s = 0.f;
        for (int d = 0; d < D_; ++d)
            s = __fadd_rn(s, __fmul_rn(row[d], row[d]));
        g_c2[k] = s;
    }
}

// ---------------------------------------------------------------------------
// prep_x: transpose (B,D,H,W)->(N,D), exact x2, fp32 copy + bf16 hi split.
// ---------------------------------------------------------------------------
__global__ __launch_bounds__(256) void prep_x(const float* __restrict__ x) {
    extern __shared__ float xs[];   // [64][257]
    const int t   = threadIdx.x;
    const int n0  = blockIdx.x * 64;
    const int b   = n0 >> 10;
    const int hw0 = n0 & 1023;
    const float* xb = x + ((size_t)b << 18) + hw0;

#pragma unroll 8
    for (int i = 0; i < 64; ++i) {
        const int e = t + (i << 8);
        const int d = e >> 6, n = e & 63;
        xs[n * 257 + d] = xb[((size_t)d << 10) + n];
    }
    __syncthreads();

    if (t < 64) {
        const float* r = xs + t * 257;
        float s = 0.f;
        for (int d = 0; d < D_; ++d)
            s = __fadd_rn(s, __fmul_rn(r[d], r[d]));
        g_x2[n0 + t] = s;
    }

#pragma unroll 8
    for (int i = 0; i < 64; ++i) {
        const int e = t + (i << 8);
        const int n = e >> 8, d = e & 255;
        const float v = xs[n * 257 + d];
        const size_t gi = ((size_t)(n0 + n) << 8) + d;
        g_xt[gi] = v;
        g_xh[gi] = __float2bfloat16(v);
    }
}

// ---------------------------------------------------------------------------
// gemm_argmin (R8 config): 2-pass HMMA GEMM s = xh*ch + xh*cl, 128-row CTA,
// B (hi+lo) 64-code chunks cp.async double-buffered, fused top-4 epilogue.
// ---------------------------------------------------------------------------
#define PITCH 264
#define SA     0
#define SB     (128 * PITCH * 2)                  // 67584
#define SB_HL  (64 * PITCH * 2)                   // 33792 (lo offset in buf)
#define SB_STRIDE (2 * 64 * PITCH * 2)            // 67584 per buf (hi+lo)
#define S_C2   (SB + 2 * SB_STRIDE)               // 202752
#define S_X2   (S_C2 + 4096)                      // 206848
#define S_CV   (S_X2 + 512)                       // 207360
#define S_CI   (S_CV + 8192)                      // 215552
#define GEMM_SMEM (S_CI + 8192)                   // 223744

__device__ __forceinline__ void stage_b(uint32_t sb, int buf, int kc, int t) {
    const uint32_t dst = sb + SB + buf * SB_STRIDE;
#pragma unroll
    for (int i = 0; i < 8; ++i) {
        const int e = t + (i << 8);               // 0..2047
        const int row = e >> 5;                   // 0..63
        const int c8 = (e & 31) << 3;             // 0..248
        const uint32_t doff = (uint32_t)(row * PITCH + c8) * 2;
        const size_t gi = ((size_t)((kc << 6) + row) << 8) + c8;
        CP_ASYNC16(dst + doff, g_ch + gi);
        CP_ASYNC16(dst + SB_HL + doff, g_cl + gi);
    }
}

__global__ __launch_bounds__(256, 1) void gemm_argmin() {
    extern __shared__ char sm[];
    __nv_bfloat16* Ah = (__nv_bfloat16*)(sm + SA);
    float* c2s = (float*)(sm + S_C2);
    float* x2s = (float*)(sm + S_X2);
    float* cvs = (float*)(sm + S_CV);
    int*   cis = (int*)(sm + S_CI);

    const int t    = threadIdx.x;
    const int lane = t & 31;
    const int n0   = blockIdx.x * 128;
    const int warpM = (t >> 5) * 16;
    const int g = lane >> 2, q = lane & 3;
    const uint32_t sb = smem_u32(sm);

    stage_b(sb, 0, 0, t);
    CP_COMMIT();

#pragma unroll
    for (int i = 0; i < 16; ++i) {
        const int e = t + (i << 8);
        const int row = e >> 5, c8 = (e & 31) << 3;
        *(uint4*)(Ah + row * PITCH + c8) =
            *(const uint4*)(g_xh + ((size_t)(n0 + row) << 8) + c8);
    }
    for (int i = t; i < K_; i += 256) c2s[i] = g_c2[i];
    if (t < 128) x2s[t] = g_x2[n0 + t];

    const uint32_t a_idx = (uint32_t)((warpM + (lane & 15)) * PITCH + ((lane >> 4) << 3));
    const uint32_t aoh = sb + SA + a_idx * 2;
    const uint32_t b_idx = (uint32_t)(((lane & 7) + ((lane >> 4) << 3)) * PITCH
                                      + (((lane >> 3) & 1) << 3));

    float tv[2][4];
    int   ti[2][4];
#pragma unroll
    for (int r = 0; r < 2; ++r)
#pragma unroll
        for (int s = 0; s < 4; ++s) { tv[r][s] = FINF; ti[r][s] = 0; }

    for (int nc = 0; nc < 16; ++nc) {
        const int buf = nc & 1;
        if (nc < 15) { stage_b(sb, buf ^ 1, nc + 1, t); CP_COMMIT(); CP_WAIT(1); }
        else         { CP_WAIT(0); }
        __syncthreads();

        const uint32_t bh = sb + SB + buf * SB_STRIDE + b_idx * 2;
        const uint32_t bl = bh + SB_HL;

        float acc[8][4];
#pragma unroll
        for (int j = 0; j < 8; ++j)
#pragma unroll
            for (int s = 0; s < 4; ++s) acc[j][s] = 0.f;

#pragma unroll 2
        for (int k = 0; k < 16; ++k) {
            uint32_t a0, a1, a2, a3;
            uint32_t fh[4][4], fl[4][4];
            LDSM_X4(a0, a1, a2, a3, aoh + k * 32);
#pragma unroll
            for (int p = 0; p < 4; ++p) {
                LDSM_X4(fh[p][0], fh[p][1], fh[p][2], fh[p][3],
                        bh + (p * 16 * PITCH) * 2 + k * 32);
                LDSM_X4(fl[p][0], fl[p][1], fl[p][2], fl[p][3],
                        bl + (p * 16 * PITCH) * 2 + k * 32);
            }
#pragma unroll
            for (int p = 0; p < 4; ++p) {
                MMA_BF16(acc[2 * p],     a0, a1, a2, a3, fh[p][0], fh[p][1]);
                MMA_BF16(acc[2 * p + 1], a0, a1, a2, a3, fh[p][2], fh[p][3]);
            }
#pragma unroll
            for (int p = 0; p < 4; ++p) {
                MMA_BF16(acc[2 * p],     a0, a1, a2, a3, fl[p][0], fl[p][1]);
                MMA_BF16(acc[2 * p + 1], a0, a1, a2, a3, fl[p][2], fl[p][3]);
            }
        }

        const float x2lo = x2s[warpM + g];
        const float x2hi = x2s[warpM + 8 + g];
#pragma unroll
        for (int j = 0; j < 8; ++j) {
            const int colb = (nc << 6) + (j << 3) + (q << 1);
            const float c2a = c2s[colb], c2b = c2s[colb + 1];
            fold4(tv[0], ti[0], __fadd_rn(__fadd_rn(x2lo, -2.f * acc[j][0]), c2a), colb);
            fold4(tv[0], ti[0], __fadd_rn(__fadd_rn(x2lo, -2.f * acc[j][1]), c2b), colb + 1);
            fold4(tv[1], ti[1], __fadd_rn(__fadd_rn(x2hi, -2.f * acc[j][2]), c2a), colb);
            fold4(tv[1], ti[1], __fadd_rn(__fadd_rn(x2hi, -2.f * acc[j][3]), c2b), colb + 1);
        }
        __syncthreads();
    }

#pragma unroll
    for (int s = 0; s < 4; ++s) {
        cvs[((warpM + g) * 4 + q) * 4 + s]     = tv[0][s];
        cis[((warpM + g) * 4 + q) * 4 + s]     = ti[0][s];
        cvs[((warpM + 8 + g) * 4 + q) * 4 + s] = tv[1][s];
        cis[((warpM + 8 + g) * 4 + q) * 4 + s] = ti[1][s];
    }
    __syncthreads();
    if (t < 128) {
        float bv[4] = {FINF, FINF, FINF, FINF};
        int   bi[4] = {0, 0, 0, 0};
#pragma unroll
        for (int qq = 0; qq < 4; ++qq)
#pragma unroll
            for (int s = 0; s < 4; ++s)
                fold4(bv, bi, cvs[(t * 4 + qq) * 4 + s], cis[(t * 4 + qq) * 4 + s]);
        const int n = n0 + t;
#pragma unroll
        for (int s = 0; s < 4; ++s) { g_cv[n][s] = bv[s]; g_ci[n][s] = bi[s]; }
    }
}

// ---------------------------------------------------------------------------
// classify: resolve unambiguous rows; compact the rest into work queues.
// ---------------------------------------------------------------------------
__global__ __launch_bounds__(256) void classify_kernel() {
    const int n = blockIdx.x * 256 + threadIdx.x;
    const float lim = g_cv[n][0] + MARGIN;
    const int ncand = 1 + (g_cv[n][1] <= lim) + (g_cv[n][2] <= lim)
                        + (g_cv[n][3] <= lim);
    if (ncand == 1) {
        g_idx[n] = g_ci[n][0];
    } else if (ncand < 4) {
        g_qa[atomicAdd(&g_qa_n, 1)] = n;
    } else {
        g_qb[atomicAdd(&g_qb_n, 1)] = n;
    }
}

// ---------------------------------------------------------------------------
// refine_small: persistent warps grid-stride over queue A (2-3 candidates).
// ---------------------------------------------------------------------------
__global__ __launch_bounds__(256) void refine_small(const float* __restrict__ cb)
{
    __shared__ float sx[8][260];
    __shared__ float sc[8][3][260];
    const int w = threadIdx.x >> 5;
    const int l = threadIdx.x & 31;
    const int wi = (blockIdx.x << 3) + w;
    const int stride = gridDim.x << 3;
    const int cnt = g_qa_n;

    for (int i = wi; i < cnt; i += stride) {
        const int n = g_qa[i];
        const float lim = g_cv[n][0] + MARGIN;
        const int ncand = 2 + (g_cv[n][2] <= lim);

        {
            const float* xr = g_xt + ((size_t)n << 8);
#pragma unroll
            for (int ii = 0; ii < 2; ++ii) {
                const int d = (l + (ii << 5)) << 2;
                *(float4*)&sx[w][d] = *(const float4*)(xr + d);
            }
        }
        for (int c = 0; c < ncand; ++c) {
            const float* cr = cb + ((size_t)g_ci[n][c] << 8);
#pragma unroll
            for (int ii = 0; ii < 2; ++ii) {
                const int d = (l + (ii << 5)) << 2;
                *(float4*)&sc[w][c][d] = *(const float4*)(cr + d);
            }
        }
        __syncwarp();

        float bestv = FINF;
        int   besti = 0x7fffffff;
        if (l < ncand) {
            const int k = g_ci[n][l];
            float s = 0.f;
#pragma unroll 16
            for (int d = 0; d < D_; ++d)
                s = fmaf(sx[w][d], sc[w][l][d], s);
            bestv = __fadd_rn(__fadd_rn(g_x2[n], -2.f * s), g_c2[k]);
            besti = k;
        }
#pragma unroll
        for (int m = 16; m; m >>= 1) {
            const float ov = __shfl_xor_sync(0xffffffffu, bestv, m);
            const int   oi = __shfl_xor_sync(0xffffffffu, besti, m);
            if (ov < bestv || (ov == bestv && oi < besti)) { bestv = ov; besti = oi; }
        }
        if (l == 0) g_idx[n] = besti;
        __syncwarp();
    }
}

// ---------------------------------------------------------------------------
// refine_full (BATCHED): 8 saturated rows per block share each staged
// 64-code chunk -> codebook traffic /8. Exact chains, first-min tie-break.
// dyn smem: 64*257 floats (scf).
// ---------------------------------------------------------------------------
__global__ __launch_bounds__(256) void refine_full(const float* __restrict__ cb)
{
    extern __shared__ float scf[];          // [64][257]
    __shared__ float sx[8][260];
    __shared__ float x2s[8];
    __shared__ int   rown[8];
    __shared__ float c2s[K_];
    __shared__ float bvS[8][64];
    __shared__ int   biS[8][64];
    const int t = threadIdx.x;
    const int cnt = g_qb_n;
    const int c = t & 63, r = t >> 6;      // code lane, row slot (r, r+4)

#pragma unroll
    for (int i = 0; i < 4; ++i) c2s[t + (i << 8)] = g_c2[t + (i << 8)];

    for (int q0 = blockIdx.x * 8; q0 < cnt; q0 += gridDim.x * 8) {
        const int nrows = min(8, cnt - q0);
        __syncthreads();
        if (t < 8 && t < nrows) {
            const int n = g_qb[q0 + t];
            rown[t] = n;
            x2s[t] = g_x2[n];
        }
        // stage x rows (coalesced float4)
#pragma unroll
        for (int i = 0; i < 2; ++i) {
            const int slot = t + (i << 8);           // 0..511
            const int rr = slot >> 6, d4 = (slot & 63) << 2;
            if (rr < nrows) {
                const int n = g_qb[q0 + rr];
                *(float4*)&sx[rr][d4] = *(const float4*)(g_xt + ((size_t)n << 8) + d4);
            }
        }

        float bv0 = FINF, bv1 = FINF;
        int   bi0 = 0x7fffffff, bi1 = 0x7fffffff;

        for (int nc = 0; nc < 16; ++nc) {
            __syncthreads();
#pragma unroll
            for (int i = 0; i < 16; ++i) {
                const int e = t + (i << 8);
                const int row = e >> 6, c4 = (e & 63) << 2;
                const float4 v = *(const float4*)(cb + ((size_t)((nc << 6) + row) << 8) + c4);
                float* dst = scf + row * 257 + c4;
                dst[0] = v.x; dst[1] = v.y; dst[2] = v.z; dst[3] = v.w;
            }
            __syncthreads();
            const int k = (nc << 6) + c;
            const float* cr = scf + c * 257;
            float s0 = 0.f, s1 = 0.f;
#pragma unroll 8
            for (int d = 0; d < D_; ++d) {
                const float cv = cr[d];
                s0 = fmaf(sx[r][d],     cv, s0);
                s1 = fmaf(sx[r + 4][d], cv, s1);
            }
            const float v0 = __fadd_rn(__fadd_rn(x2s[r],     -2.f * s0), c2s[k]);
            const float v1 = __fadd_rn(__fadd_rn(x2s[r + 4], -2.f * s1), c2s[k]);
            if (v0 < bv0) { bv0 = v0; bi0 = k; }   // k ascending per lane
            if (v1 < bv1) { bv1 = v1; bi1 = k; }
        }

        bvS[r][c] = bv0;     biS[r][c] = bi0;
        bvS[r + 4][c] = bv1; biS[r + 4][c] = bi1;
        __syncthreads();

        // warp w reduces row w (64 candidates)
        const int w = t >> 5, l = t & 31;
        if (w < nrows) {
            float v = bvS[w][l];        int kk = biS[w][l];
            const float v2 = bvS[w][l + 32]; const int k2 = biS[w][l + 32];
            if (v2 < v || (v2 == v && k2 < kk)) { v = v2; kk = k2; }
#pragma unroll
            for (int m = 16; m; m >>= 1) {
                const float ov = __shfl_xor_sync(0xffffffffu, v, m);
                const int   oi = __shfl_xor_sync(0xffffffffu, kk, m);
                if (ov < v || (ov == v && oi < kk)) { v = ov; kk = oi; }
            }
            if (l == 0) g_idx[rown[w]] = kk;
        }
    }
}

// ---------------------------------------------------------------------------
// gather + straight-through output + loss partials + idx-as-float
// ---------------------------------------------------------------------------
__global__ __launch_bounds__(256) void quant_kernel(
    const float* __restrict__ x, const float* __restrict__ cb,
    float* __restrict__ out, long long out_size)
{
    __shared__ float red[256];
    const int t   = threadIdx.x;
    const int n0  = blockIdx.x * 64;
    const int b   = n0 / HW_;
    const int hw0 = n0 % HW_;
    const int tn  = t & 63;
    const int dz  = t >> 6;
    const int n   = n0 + tn;
    const int k   = g_idx[n];

    const float* xb = x   + (size_t)b * D_ * HW_ + hw0 + tn;
    float*       ob = out + (size_t)b * D_ * HW_ + hw0 + tn;
    const float* cr = cb  + (size_t)k * D_;

    float s = 0.f;
#pragma unroll 8
    for (int d = dz; d < D_; d += 4) {
        const float xv   = xb[(size_t)d * HW_];
        const float cv   = cr[d];
        const float diff = __fadd_rn(cv, -xv);
        ob[(size_t)d * HW_] = __fadd_rn(xv, diff);
        s = fmaf(diff, diff, s);
    }

    if (dz == 0 && out_size >= Q_OFF + 3 + N_)
        out[Q_OFF + 3 + n] = (float)k;

    red[t] = s;
    __syncthreads();
    for (int w = 128; w > 0; w >>= 1) {
        if (t < w) red[t] += red[t + w];
        __syncthreads();
    }
    if (t == 0) atomicAdd(&g_acc, (double)red[0]);
}

__global__ void finalize_kernel(float* __restrict__ out, long long out_size) {
    if (out_size >= Q_OFF + 3) {
        const double m = g_acc / (double)((long long)N_ * D_);
        const float  l = (float)m;
        out[Q_OFF + 0] = l;
        out[Q_OFF + 1] = l;
        out[Q_OFF + 2] = __fadd_rn(l, 0.25f * l);
    }
}

// ---------------------------------------------------------------------------
extern "C" void kernel_launch(void* const* d_in, const int* in_sizes, int n_in,
                              void* d_out, int out_size)
{
    const float* x  = (const float*)d_in[0];
    const float* cb = (const float*)d_in[1];
    float*       out = (float*)d_out;
    const long long osz = (long long)out_size;

    cudaFuncSetAttribute(prep_x,
        cudaFuncAttributeMaxDynamicSharedMemorySize, 64 * 257 * 4);
    cudaFuncSetAttribute(gemm_argmin,
        cudaFuncAttributeMaxDynamicSharedMemorySize, GEMM_SMEM);
    cudaFuncSetAttribute(refine_full,
        cudaFuncAttributeMaxDynamicSharedMemorySize, 64 * 257 * 4);

    zero_kernel<<<1, 1>>>();                       // launch 1
    prep_cb<<<K_, 256>>>(cb);                      // launch 2
    zero_kernel<<<1, 1>>>();                       // launch 3 (slot filler)
    prep_x<<<512, 256, 64 * 257 * 4>>>(x);         // launch 4 (ncu target)
    gemm_argmin<<<N_ / 128, 256, GEMM_SMEM>>>();   // launch 5
    classify_kernel<<<N_ / 256, 256>>>();          // launch 6
    refine_small<<<256, 256>>>(cb);                // launch 7
    refine_full<<<64, 256, 64 * 257 * 4>>>(cb);    // launch 8
    quant_kernel<<<N_ / 64, 256>>>(x, cb, out, osz);
    finalize_kernel<<<1, 1>>>(out, osz);
}

// round 11
// speedup vs baseline: 1.6935x; 1.1223x over previous
#include <cuda_runtime.h>
#include <cuda_bf16.h>
#include <cstdint>

#define B_   32
#define D_   256
#define HW_  1024
#define N_   32768
#define K_   1024
#define MARGIN 3e-4f
#define FINF 3.4e38f

static const long long Q_OFF = 8388608LL;   // B*D*H*W

// ---------------- device globals ----------------
__device__ int    g_idx[N_];
__device__ float  g_c2[K_];
__device__ float  g_x2[N_];
__device__ double g_acc;
__device__ __align__(16) float         g_xt[(size_t)N_ * D_];
__device__ __align__(16) __nv_bfloat16 g_xh[(size_t)N_ * D_];
__device__ __align__(16) __nv_bfloat16 g_ch[(size_t)K_ * D_];
__device__ __align__(16) __nv_bfloat16 g_cl[(size_t)K_ * D_];
__device__ float g_cv[N_][4];
__device__ int   g_ci[N_][4];
__device__ int   g_qa[N_];
__device__ int   g_qb[N_];
__device__ int   g_qa_n;
__device__ int   g_qb_n;

__device__ __forceinline__ uint32_t smem_u32(const void* p) {
    uint32_t a;
    asm("{ .reg .u64 t; cvta.to.shared.u64 t, %1; cvt.u32.u64 %0, t; }"
        : "=r"(a) : "l"(p));
    return a;
}
#define LDSM_X4(r0, r1, r2, r3, addr) \
    asm volatile("ldmatrix.sync.aligned.m8n8.x4.shared.b16 {%0,%1,%2,%3}, [%4];" \
                 : "=r"(r0), "=r"(r1), "=r"(r2), "=r"(r3) : "r"(addr))
#define MMA_BF16(c, a0, a1, a2, a3, b0, b1) \
    asm volatile("mma.sync.aligned.m16n8k16.row.col.f32.bf16.bf16.f32 " \
                 "{%0,%1,%2,%3}, {%4,%5,%6,%7}, {%8,%9}, {%0,%1,%2,%3};" \
                 : "+f"((c)[0]), "+f"((c)[1]), "+f"((c)[2]), "+f"((c)[3]) \
                 : "r"(a0), "r"(a1), "r"(a2), "r"(a3), "r"(b0), "r"(b1))
#define CP_ASYNC16(dst, src) \
    asm volatile("cp.async.cg.shared.global [%0], [%1], 16;" \
                 :: "r"(dst), "l"(src))
#define CP_COMMIT() asm volatile("cp.async.commit_group;" ::: "memory")
#define CP_WAIT(n)  asm volatile("cp.async.wait_group %0;" :: "n"(n) : "memory")

__device__ __forceinline__ void fold4(float* v, int* ix, float nv, int nk) {
    if (nv < v[3]) {
        if (nv < v[2]) {
            v[3] = v[2]; ix[3] = ix[2];
            if (nv < v[1]) {
                v[2] = v[1]; ix[2] = ix[1];
                if (nv < v[0]) { v[1] = v[0]; ix[1] = ix[0]; v[0] = nv; ix[0] = nk; }
                else           { v[1] = nv; ix[1] = nk; }
            } else { v[2] = nv; ix[2] = nk; }
        } else { v[3] = nv; ix[3] = nk; }
    }
}

// ---------------------------------------------------------------------------
__global__ void zero_kernel() { g_acc = 0.0; g_qa_n = 0; g_qb_n = 0; }

// ---------------------------------------------------------------------------
// prep_cb: bf16 hi/lo split; exact c2 (sequential no-FMA).
// ---------------------------------------------------------------------------
__global__ __launch_bounds__(256) void prep_cb(const float* __restrict__ cb) {
    __shared__ float row[256];
    const int k = blockIdx.x, t = threadIdx.x;
    const float v = cb[(size_t)k * D_ + t];
    row[t] = v;
    const __nv_bfloat16 h = __float2bfloat16(v);
    const __nv_bfloat16 l = __float2bfloat16(__fsub_rn(v, __bfloat162float(h)));
    g_ch[(size_t)k * D_ + t] = h;
    g_cl[(size_t)k * D_ + t] = l;
    __syncthreads();
    if (t == 0) {
        float s = 0.f;
        for (int d = 0; d < D_; ++d)
            s = __fadd_rn(s, __fmul_rn(row[d], row[d]));
        g_c2[k] = s;
    }
}

// ---------------------------------------------------------------------------
// prep_x v2: float4 transpose loads, x2 chain overlapped with split-writes
// (warps 2-7 bypass it), packed float2/bf16x2 writes.
// dyn smem: 64*257 floats.
// ---------------------------------------------------------------------------
__global__ __launch_bounds__(256) void prep_x(const float* __restrict__ x) {
    extern __shared__ float xs[];   // [64 n][257 d] (pitch 257)
    const int t   = threadIdx.x;
    const int n0  = blockIdx.x * 64;
    const int b   = n0 >> 10;
    const int hw0 = n0 & 1023;
    const float* xb = x + ((size_t)b << 18) + hw0;

    // phase 1: float4 loads over n (coalesced), scatter to [n][d] smem
#pragma unroll
    for (int i = 0; i < 16; ++i) {
        const int e  = t + (i << 8);        // 0..4095
        const int d  = e >> 4;              // 0..255
        const int n4 = (e & 15) << 2;       // 0..60
        const float4 v = *(const float4*)(xb + ((size_t)d << 10) + n4);
        xs[(n4 + 0) * 257 + d] = v.x;
        xs[(n4 + 1) * 257 + d] = v.y;
        xs[(n4 + 2) * 257 + d] = v.z;
        xs[(n4 + 3) * 257 + d] = v.w;
    }
    __syncthreads();

    // x2 chain: only warps 0-1; warps 2-7 fall through to the write phase
    if (t < 64) {
        const float* r = xs + t * 257;
        float s = 0.f;
        for (int d = 0; d < D_; ++d)
            s = __fadd_rn(s, __fmul_rn(r[d], r[d]));
        g_x2[n0 + t] = s;
    }

    // write phase: packed float2 (g_xt) + bf16x2 (g_xh), coalesced
#pragma unroll
    for (int i = 0; i < 32; ++i) {
        const int e  = t + (i << 8);        // 0..8191
        const int n  = e >> 7;              // 0..63
        const int d2 = (e & 127) << 1;      // 0..254
        const float v0 = xs[n * 257 + d2];
        const float v1 = xs[n * 257 + d2 + 1];
        const size_t gi = ((size_t)(n0 + n) << 8) + d2;
        *(float2*)(g_xt + gi) = make_float2(v0, v1);
        __nv_bfloat162 hp;
        hp.x = __float2bfloat16(v0);
        hp.y = __float2bfloat16(v1);
        *(__nv_bfloat162*)(g_xh + gi) = hp;
    }
}

// ---------------------------------------------------------------------------
// gemm_argmin: 2-pass HMMA GEMM s = xh*ch + xh*cl, 128-row CTA, 512 threads
// (16 warps = 8 M-tiles x 2 N-halves, 4 warps/SMSP), B (hi+lo) 64-code
// chunks cp.async double-buffered, fused top-4 epilogue.
// ---------------------------------------------------------------------------
#define PITCH 264
#define SA     0
#define SB     (128 * PITCH * 2)                  // 67584
#define SB_HL  (64 * PITCH * 2)                   // 33792 (lo offset in buf)
#define SB_STRIDE (2 * 64 * PITCH * 2)            // 67584 per buf (hi+lo)
#define S_C2   (SB + 2 * SB_STRIDE)               // 202752
#define S_X2   (S_C2 + 4096)                      // 206848
#define S_MGV  (S_X2 + 512)                       // 207360 (128*2*4 floats)
#define S_MGI  (S_MGV + 4096)                     // 211456
#define GEMM_SMEM (S_MGI + 4096)                  // 215552

__device__ __forceinline__ void stage_b(uint32_t sb, int buf, int kc, int t) {
    const uint32_t dst = sb + SB + buf * SB_STRIDE;
#pragma unroll
    for (int i = 0; i < 4; ++i) {
        const int e = t + (i << 9);               // 0..2047
        const int row = e >> 5;                   // 0..63
        const int c8 = (e & 31) << 3;             // 0..248
        const uint32_t doff = (uint32_t)(row * PITCH + c8) * 2;
        const size_t gi = ((size_t)((kc << 6) + row) << 8) + c8;
        CP_ASYNC16(dst + doff, g_ch + gi);
        CP_ASYNC16(dst + SB_HL + doff, g_cl + gi);
    }
}

__global__ __launch_bounds__(512, 1) void gemm_argmin() {
    extern __shared__ char sm[];
    __nv_bfloat16* Ah = (__nv_bfloat16*)(sm + SA);
    float* c2s = (float*)(sm + S_C2);
    float* x2s = (float*)(sm + S_X2);
    float* mgv = (float*)(sm + S_MGV);
    int*   mgi = (int*)(sm + S_MGI);

    const int t    = threadIdx.x;
    const int lane = t & 31;
    const int w    = t >> 5;                      // 0..15
    const int wm   = (w >> 1) << 4;               // M-tile base row (0..112)
    const int wn   = (w & 1);                     // N half of chunk
    const int n0   = blockIdx.x * 128;
    const int g = lane >> 2, q = lane & 3;
    const uint32_t sb = smem_u32(sm);

    stage_b(sb, 0, 0, t);
    CP_COMMIT();

    // resident A (hi), c2, x2
#pragma unroll
    for (int i = 0; i < 8; ++i) {
        const int e = t + (i << 9);
        const int row = e >> 5, c8 = (e & 31) << 3;
        *(uint4*)(Ah + row * PITCH + c8) =
            *(const uint4*)(g_xh + ((size_t)(n0 + row) << 8) + c8);
    }
#pragma unroll
    for (int i = 0; i < 2; ++i) c2s[t + (i << 9)] = g_c2[t + (i << 9)];
    if (t < 128) x2s[t] = g_x2[n0 + t];

    const uint32_t a_idx = (uint32_t)((wm + (lane & 15)) * PITCH + ((lane >> 4) << 3));
    const uint32_t aoh = sb + SA + a_idx * 2;
    const uint32_t b_idx = (uint32_t)(((lane & 7) + ((lane >> 4) << 3)) * PITCH
                                      + (((lane >> 3) & 1) << 3));
    const uint32_t bgrp = (uint32_t)((wn << 5) * PITCH) * 2;   // N-half offset

    float tv[2][4];
    int   ti[2][4];
#pragma unroll
    for (int r = 0; r < 2; ++r)
#pragma unroll
        for (int s = 0; s < 4; ++s) { tv[r][s] = FINF; ti[r][s] = 0; }

    for (int nc = 0; nc < 16; ++nc) {
        const int buf = nc & 1;
        if (nc < 15) { stage_b(sb, buf ^ 1, nc + 1, t); CP_COMMIT(); CP_WAIT(1); }
        else         { CP_WAIT(0); }
        __syncthreads();

        const uint32_t bh = sb + SB + buf * SB_STRIDE + bgrp + b_idx * 2;
        const uint32_t bl = bh + SB_HL;

        float acc[4][4];
#pragma unroll
        for (int j = 0; j < 4; ++j)
#pragma unroll
            for (int s = 0; s < 4; ++s) acc[j][s] = 0.f;

#pragma unroll 4
        for (int k = 0; k < 16; ++k) {
            uint32_t a0, a1, a2, a3;
            uint32_t h00, h01, h02, h03, h10, h11, h12, h13;
            uint32_t l00, l01, l02, l03, l10, l11, l12, l13;
            LDSM_X4(a0, a1, a2, a3, aoh + k * 32);
            LDSM_X4(h00, h01, h02, h03, bh + k * 32);
            LDSM_X4(h10, h11, h12, h13, bh + 16 * PITCH * 2 + k * 32);
            LDSM_X4(l00, l01, l02, l03, bl + k * 32);
            LDSM_X4(l10, l11, l12, l13, bl + 16 * PITCH * 2 + k * 32);
            MMA_BF16(acc[0], a0, a1, a2, a3, h00, h01);
            MMA_BF16(acc[1], a0, a1, a2, a3, h02, h03);
            MMA_BF16(acc[2], a0, a1, a2, a3, h10, h11);
            MMA_BF16(acc[3], a0, a1, a2, a3, h12, h13);
            MMA_BF16(acc[0], a0, a1, a2, a3, l00, l01);
            MMA_BF16(acc[1], a0, a1, a2, a3, l02, l03);
            MMA_BF16(acc[2], a0, a1, a2, a3, l10, l11);
            MMA_BF16(acc[3], a0, a1, a2, a3, l12, l13);
        }

        // epilogue: fold this warp's 32 columns into per-thread top-4
        const float x2lo = x2s[wm + g];
        const float x2hi = x2s[wm + 8 + g];
#pragma unroll
        for (int j = 0; j < 4; ++j) {
            const int colb = (nc << 6) + (wn << 5) + (j << 3) + (q << 1);
            const float c2a = c2s[colb], c2b = c2s[colb + 1];
            fold4(tv[0], ti[0], __fadd_rn(__fadd_rn(x2lo, -2.f * acc[j][0]), c2a), colb);
            fold4(tv[0], ti[0], __fadd_rn(__fadd_rn(x2lo, -2.f * acc[j][1]), c2b), colb + 1);
            fold4(tv[1], ti[1], __fadd_rn(__fadd_rn(x2hi, -2.f * acc[j][2]), c2a), colb);
            fold4(tv[1], ti[1], __fadd_rn(__fadd_rn(x2hi, -2.f * acc[j][3]), c2b), colb + 1);
        }
        __syncthreads();
    }

    // merge across the 4 q-lanes via shuffles
#pragma unroll
    for (int r = 0; r < 2; ++r) {
#pragma unroll
        for (int m = 1; m <= 2; m <<= 1) {
            float ov[4]; int oi[4];
#pragma unroll
            for (int s = 0; s < 4; ++s) {
                ov[s] = __shfl_xor_sync(0xffffffffu, tv[r][s], m);
                oi[s] = __shfl_xor_sync(0xffffffffu, ti[r][s], m);
            }
#pragma unroll
            for (int s = 0; s < 4; ++s) fold4(tv[r], ti[r], ov[s], oi[s]);
        }
    }
    if (q == 0) {
        const int row0 = wm + g, row1 = wm + 8 + g;
#pragma unroll
        for (int s = 0; s < 4; ++s) {
            mgv[(row0 * 2 + wn) * 4 + s] = tv[0][s];
            mgi[(row0 * 2 + wn) * 4 + s] = ti[0][s];
            mgv[(row1 * 2 + wn) * 4 + s] = tv[1][s];
            mgi[(row1 * 2 + wn) * 4 + s] = ti[1][s];
        }
    }
    __syncthreads();
    if (t < 128) {
        float bv[4] = {FINF, FINF, FINF, FINF};
        int   bi[4] = {0, 0, 0, 0};
#pragma unroll
        for (int h = 0; h < 2; ++h)
#pragma unroll
            for (int s = 0; s < 4; ++s)
                fold4(bv, bi, mgv[(t * 2 + h) * 4 + s], mgi[(t * 2 + h) * 4 + s]);
        const int n = n0 + t;
#pragma unroll
        for (int s = 0; s < 4; ++s) { g_cv[n][s] = bv[s]; g_ci[n][s] = bi[s]; }
    }
}

// ---------------------------------------------------------------------------
// classify: resolve unambiguous rows; compact the rest into work queues.
// ---------------------------------------------------------------------------
__global__ __launch_bounds__(256) void classify_kernel() {
    const int n = blockIdx.x * 256 + threadIdx.x;
    const float lim = g_cv[n][0] + MARGIN;
    const int ncand = 1 + (g_cv[n][1] <= lim) + (g_cv[n][2] <= lim)
                        + (g_cv[n][3] <= lim);
    if (ncand == 1) {
        g_idx[n] = g_ci[n][0];
    } else if (ncand < 4) {
        g_qa[atomicAdd(&g_qa_n, 1)] = n;
    } else {
        g_qb[atomicAdd(&g_qb_n, 1)] = n;
    }
}

// ---------------------------------------------------------------------------
// refine_small: persistent warps grid-stride over queue A (2-3 candidates).
// ---------------------------------------------------------------------------
__global__ __launch_bounds__(256) void refine_small(const float* __restrict__ cb)
{
    __shared__ float sx[8][260];
    __shared__ float sc[8][3][260];
    const int w = threadIdx.x >> 5;
    const int l = threadIdx.x & 31;
    const int wi = (blockIdx.x << 3) + w;
    const int stride = gridDim.x << 3;
    const int cnt = g_qa_n;

    for (int i = wi; i < cnt; i += stride) {
        const int n = g_qa[i];
        const float lim = g_cv[n][0] + MARGIN;
        const int ncand = 2 + (g_cv[n][2] <= lim);

        {
            const float* xr = g_xt + ((size_t)n << 8);
#pragma unroll
            for (int ii = 0; ii < 2; ++ii) {
                const int d = (l + (ii << 5)) << 2;
                *(float4*)&sx[w][d] = *(const float4*)(xr + d);
            }
        }
        for (int c = 0; c < ncand; ++c) {
            const float* cr = cb + ((size_t)g_ci[n][c] << 8);
#pragma unroll
            for (int ii = 0; ii < 2; ++ii) {
                const int d = (l + (ii << 5)) << 2;
                *(float4*)&sc[w][c][d] = *(const float4*)(cr + d);
            }
        }
        __syncwarp();

        float bestv = FINF;
        int   besti = 0x7fffffff;
        if (l < ncand) {
            const int k = g_ci[n][l];
            float s = 0.f;
#pragma unroll 16
            for (int d = 0; d < D_; ++d)
                s = fmaf(sx[w][d], sc[w][l][d], s);
            bestv = __fadd_rn(__fadd_rn(g_x2[n], -2.f * s), g_c2[k]);
            besti = k;
        }
#pragma unroll
        for (int m = 16; m; m >>= 1) {
            const float ov = __shfl_xor_sync(0xffffffffu, bestv, m);
            const int   oi = __shfl_xor_sync(0xffffffffu, besti, m);
            if (ov < bestv || (ov == bestv && oi < besti)) { bestv = ov; besti = oi; }
        }
        if (l == 0) g_idx[n] = besti;
        __syncwarp();
    }
}

// ---------------------------------------------------------------------------
// refine_full (batched): 8 saturated rows per block share each staged
// 64-code chunk. Exact chains, first-min tie-break. dyn smem: 64*257 floats.
// ---------------------------------------------------------------------------
__global__ __launch_bounds__(256) void refine_full(const float* __restrict__ cb)
{
    extern __shared__ float scf[];          // [64][257]
    __shared__ float sx[8][260];
    __shared__ float x2s[8];
    __shared__ int   rown[8];
    __shared__ float c2s[K_];
    __shared__ float bvS[8][64];
    __shared__ int   biS[8][64];
    const int t = threadIdx.x;
    const int cnt = g_qb_n;
    const int c = t & 63, r = t >> 6;

#pragma unroll
    for (int i = 0; i < 4; ++i) c2s[t + (i << 8)] = g_c2[t + (i << 8)];

    for (int q0 = blockIdx.x * 8; q0 < cnt; q0 += gridDim.x * 8) {
        const int nrows = min(8, cnt - q0);
        __syncthreads();
        if (t < 8 && t < nrows) {
            const int n = g_qb[q0 + t];
            rown[t] = n;
            x2s[t] = g_x2[n];
        }
#pragma unroll
        for (int i = 0; i < 2; ++i) {
            const int slot = t + (i << 8);
            const int rr = slot >> 6, d4 = (slot & 63) << 2;
            if (rr < nrows) {
                const int n = g_qb[q0 + rr];
                *(float4*)&sx[rr][d4] = *(const float4*)(g_xt + ((size_t)n << 8) + d4);
            }
        }

        float bv0 = FINF, bv1 = FINF;
        int   bi0 = 0x7fffffff, bi1 = 0x7fffffff;

        for (int nc = 0; nc < 16; ++nc) {
            __syncthreads();
#pragma unroll
            for (int i = 0; i < 16; ++i) {
                const int e = t + (i << 8);
                const int row = e >> 6, c4 = (e & 63) << 2;
                const float4 v = *(const float4*)(cb + ((size_t)((nc << 6) + row) << 8) + c4);
                float* dst = scf + row * 257 + c4;
                dst[0] = v.x; dst[1] = v.y; dst[2] = v.z; dst[3] = v.w;
            }
            __syncthreads();
            const int k = (nc << 6) + c;
            const float* cr = scf + c * 257;
            float s0 = 0.f, s1 = 0.f;
#pragma unroll 8
            for (int d = 0; d < D_; ++d) {
                const float cv = cr[d];
                s0 = fmaf(sx[r][d],     cv, s0);
                s1 = fmaf(sx[r + 4][d], cv, s1);
            }
            const float v0 = __fadd_rn(__fadd_rn(x2s[r],     -2.f * s0), c2s[k]);
            const float v1 = __fadd_rn(__fadd_rn(x2s[r + 4], -2.f * s1), c2s[k]);
            if (v0 < bv0) { bv0 = v0; bi0 = k; }
            if (v1 < bv1) { bv1 = v1; bi1 = k; }
        }

        bvS[r][c] = bv0;     biS[r][c] = bi0;
        bvS[r + 4][c] = bv1; biS[r + 4][c] = bi1;
        __syncthreads();

        const int w = t >> 5, l = t & 31;
        if (w < nrows) {
            float v = bvS[w][l];        int kk = biS[w][l];
            const float v2 = bvS[w][l + 32]; const int k2 = biS[w][l + 32];
            if (v2 < v || (v2 == v && k2 < kk)) { v = v2; kk = k2; }
#pragma unroll
            for (int m = 16; m; m >>= 1) {
                const float ov = __shfl_xor_sync(0xffffffffu, v, m);
                const int   oi = __shfl_xor_sync(0xffffffffu, kk, m);
                if (ov < v || (ov == v && oi < kk)) { v = ov; kk = oi; }
            }
            if (l == 0) g_idx[rown[w]] = kk;
        }
    }
}

// ---------------------------------------------------------------------------
// gather + straight-through output + loss partials + idx-as-float
// ---------------------------------------------------------------------------
__global__ __launch_bounds__(256) void quant_kernel(
    const float* __restrict__ x, const float* __restrict__ cb,
    float* __restrict__ out, long long out_size)
{
    __shared__ float red[256];
    const int t   = threadIdx.x;
    const int n0  = blockIdx.x * 64;
    const int b   = n0 / HW_;
    const int hw0 = n0 % HW_;
    const int tn  = t & 63;
    const int dz  = t >> 6;
    const int n   = n0 + tn;
    const int k   = g_idx[n];

    const float* xb = x   + (size_t)b * D_ * HW_ + hw0 + tn;
    float*       ob = out + (size_t)b * D_ * HW_ + hw0 + tn;
    const float* cr = cb  + (size_t)k * D_;

    float s = 0.f;
#pragma unroll 8
    for (int d = dz; d < D_; d += 4) {
        const float xv   = xb[(size_t)d * HW_];
        const float cv   = cr[d];
        const float diff = __fadd_rn(cv, -xv);
        ob[(size_t)d * HW_] = __fadd_rn(xv, diff);
        s = fmaf(diff, diff, s);
    }

    if (dz == 0 && out_size >= Q_OFF + 3 + N_)
        out[Q_OFF + 3 + n] = (float)k;

    red[t] = s;
    __syncthreads();
    for (int w = 128; w > 0; w >>= 1) {
        if (t < w) red[t] += red[t + w];
        __syncthreads();
    }
    if (t == 0) atomicAdd(&g_acc, (double)red[0]);
}

__global__ void finalize_kernel(float* __restrict__ out, long long out_size) {
    if (out_size >= Q_OFF + 3) {
        const double m = g_acc / (double)((long long)N_ * D_);
        const float  l = (float)m;
        out[Q_OFF + 0] = l;
        out[Q_OFF + 1] = l;
        out[Q_OFF + 2] = __fadd_rn(l, 0.25f * l);
    }
}

// ---------------------------------------------------------------------------
extern "C" void kernel_launch(void* const* d_in, const int* in_sizes, int n_in,
                              void* d_out, int out_size)
{
    const float* x  = (const float*)d_in[0];
    const float* cb = (const float*)d_in[1];
    float*       out = (float*)d_out;
    const long long osz = (long long)out_size;

    cudaFuncSetAttribute(prep_x,
        cudaFuncAttributeMaxDynamicSharedMemorySize, 64 * 257 * 4);
    cudaFuncSetAttribute(gemm_argmin,
        cudaFuncAttributeMaxDynamicSharedMemorySize, GEMM_SMEM);
    cudaFuncSetAttribute(refine_full,
        cudaFuncAttributeMaxDynamicSharedMemorySize, 64 * 257 * 4);

    zero_kernel<<<1, 1>>>();                       // launch 1
    prep_cb<<<K_, 256>>>(cb);                      // launch 2
    prep_x<<<512, 256, 64 * 257 * 4>>>(x);         // launch 3
    gemm_argmin<<<N_ / 128, 512, GEMM_SMEM>>>();   // launch 4 (ncu target)
    classify_kernel<<<N_ / 256, 256>>>();          // launch 5
    refine_small<<<256, 256>>>(cb);                // launch 6
    refine_full<<<64, 256, 64 * 257 * 4>>>(cb);    // launch 7
    quant_kernel<<<N_ / 64, 256>>>(x, cb, out, osz);
    finalize_kernel<<<1, 1>>>(out, osz);
}

// round 12
// speedup vs baseline: 1.7980x; 1.0617x over previous
#include <cuda_runtime.h>
#include <cuda_bf16.h>
#include <cstdint>

#define B_   32
#define D_   256
#define HW_  1024
#define N_   32768
#define K_   1024
#define MARGIN 3e-4f
#define FINF 3.4e38f

static const long long Q_OFF = 8388608LL;   // B*D*H*W

// ---------------- device globals ----------------
__device__ int    g_idx[N_];
__device__ float  g_c2[K_];
__device__ float  g_x2[N_];
__device__ double g_acc;
__device__ __align__(16) float         g_xt[(size_t)N_ * D_];
__device__ __align__(16) __nv_bfloat16 g_xh[(size_t)N_ * D_];
__device__ __align__(16) __nv_bfloat16 g_ch[(size_t)K_ * D_];
__device__ __align__(16) __nv_bfloat16 g_cl[(size_t)K_ * D_];
__device__ float g_cv[N_][4];
__device__ int   g_ci[N_][4];
__device__ int   g_qa[N_];
__device__ int   g_qb[N_];
__device__ int   g_qa_n;
__device__ int   g_qb_n;

__device__ __forceinline__ uint32_t smem_u32(const void* p) {
    uint32_t a;
    asm("{ .reg .u64 t; cvta.to.shared.u64 t, %1; cvt.u32.u64 %0, t; }"
        : "=r"(a) : "l"(p));
    return a;
}
#define LDSM_X4(r0, r1, r2, r3, addr) \
    asm volatile("ldmatrix.sync.aligned.m8n8.x4.shared.b16 {%0,%1,%2,%3}, [%4];" \
                 : "=r"(r0), "=r"(r1), "=r"(r2), "=r"(r3) : "r"(addr))
#define MMA_BF16(c, a0, a1, a2, a3, b0, b1) \
    asm volatile("mma.sync.aligned.m16n8k16.row.col.f32.bf16.bf16.f32 " \
                 "{%0,%1,%2,%3}, {%4,%5,%6,%7}, {%8,%9}, {%0,%1,%2,%3};" \
                 : "+f"((c)[0]), "+f"((c)[1]), "+f"((c)[2]), "+f"((c)[3]) \
                 : "r"(a0), "r"(a1), "r"(a2), "r"(a3), "r"(b0), "r"(b1))
#define CP_ASYNC16(dst, src) \
    asm volatile("cp.async.cg.shared.global [%0], [%1], 16;" \
                 :: "r"(dst), "l"(src))
#define CP_COMMIT() asm volatile("cp.async.commit_group;" ::: "memory")
#define CP_WAIT(n)  asm volatile("cp.async.wait_group %0;" :: "n"(n) : "memory")

__device__ __forceinline__ void fold4(float* v, int* ix, float nv, int nk) {
    if (nv < v[3]) {
        if (nv < v[2]) {
            v[3] = v[2]; ix[3] = ix[2];
            if (nv < v[1]) {
                v[2] = v[1]; ix[2] = ix[1];
                if (nv < v[0]) { v[1] = v[0]; ix[1] = ix[0]; v[0] = nv; ix[0] = nk; }
                else           { v[1] = nv; ix[1] = nk; }
            } else { v[2] = nv; ix[2] = nk; }
        } else { v[3] = nv; ix[3] = nk; }
    }
}

// ---------------------------------------------------------------------------
__global__ void zero_kernel() { g_acc = 0.0; g_qa_n = 0; g_qb_n = 0; }

// ---------------------------------------------------------------------------
// prep_cb: bf16 hi/lo split; exact c2 (sequential no-FMA).
// ---------------------------------------------------------------------------
__global__ __launch_bounds__(256) void prep_cb(const float* __restrict__ cb) {
    __shared__ float row[256];
    const int k = blockIdx.x, t = threadIdx.x;
    const float v = cb[(size_t)k * D_ + t];
    row[t] = v;
    const __nv_bfloat16 h = __float2bfloat16(v);
    const __nv_bfloat16 l = __float2bfloat16(__fsub_rn(v, __bfloat162float(h)));
    g_ch[(size_t)k * D_ + t] = h;
    g_cl[(size_t)k * D_ + t] = l;
    __syncthreads();
    if (t == 0) {
        float s = 0.f;
        for (int d = 0; d < D_; ++d)
            s = __fadd_rn(s, __fmul_rn(row[d], row[d]));
        g_c2[k] = s;
    }
}

// ---------------------------------------------------------------------------
// prep_x: float4 transpose loads, x2 chain on warps 0-1 (others bypass),
// packed float2/bf16x2 writes. dyn smem: 64*257 floats.
// ---------------------------------------------------------------------------
__global__ __launch_bounds__(256) void prep_x(const float* __restrict__ x) {
    extern __shared__ float xs[];   // [64 n][257 d]
    const int t   = threadIdx.x;
    const int n0  = blockIdx.x * 64;
    const int b   = n0 >> 10;
    const int hw0 = n0 & 1023;
    const float* xb = x + ((size_t)b << 18) + hw0;

#pragma unroll
    for (int i = 0; i < 16; ++i) {
        const int e  = t + (i << 8);
        const int d  = e >> 4;
        const int n4 = (e & 15) << 2;
        const float4 v = *(const float4*)(xb + ((size_t)d << 10) + n4);
        xs[(n4 + 0) * 257 + d] = v.x;
        xs[(n4 + 1) * 257 + d] = v.y;
        xs[(n4 + 2) * 257 + d] = v.z;
        xs[(n4 + 3) * 257 + d] = v.w;
    }
    __syncthreads();

    if (t < 64) {
        const float* r = xs + t * 257;
        float s = 0.f;
        for (int d = 0; d < D_; ++d)
            s = __fadd_rn(s, __fmul_rn(r[d], r[d]));
        g_x2[n0 + t] = s;
    }

#pragma unroll
    for (int i = 0; i < 32; ++i) {
        const int e  = t + (i << 8);
        const int n  = e >> 7;
        const int d2 = (e & 127) << 1;
        const float v0 = xs[n * 257 + d2];
        const float v1 = xs[n * 257 + d2 + 1];
        const size_t gi = ((size_t)(n0 + n) << 8) + d2;
        *(float2*)(g_xt + gi) = make_float2(v0, v1);
        __nv_bfloat162 hp;
        hp.x = __float2bfloat16(v0);
        hp.y = __float2bfloat16(v1);
        *(__nv_bfloat162*)(g_xh + gi) = hp;
    }
}

// ---------------------------------------------------------------------------
// gemm_argmin: 2-pass HMMA (s = xh*ch + xh*cl). 128-row CTA, 512 threads =
// 16 warps as 4 M-tiles(32 rows) x 4 N-quarters(32 codes) over 128-code
// chunks (single-buffered cp.async). Warp tile 32x32: 6 LDSM / 16 MMA per
// k-step. Fused top-4 epilogue.
// ---------------------------------------------------------------------------
#define PITCH 264
#define SA     0
#define SB     (128 * PITCH * 2)                  // 67584
#define SB_HL  (128 * PITCH * 2)                  // lo offset from hi base
#define S_C2   (SB + 2 * SB_HL)                   // 202752
#define S_X2   (S_C2 + 4096)                      // 206848
#define S_MGV  (S_X2 + 512)                       // 207360 (128*4*4 floats)
#define S_MGI  (S_MGV + 8192)                     // 215552
#define GEMM_SMEM (S_MGI + 8192)                  // 223744

__device__ __forceinline__ void stage_b(uint32_t sb, int kc, int t) {
    const uint32_t dst = sb + SB;
#pragma unroll
    for (int i = 0; i < 8; ++i) {
        const int e = t + (i << 9);               // 0..4095
        const int row = e >> 5;                   // 0..127
        const int c8 = (e & 31) << 3;             // 0..248
        const uint32_t doff = (uint32_t)(row * PITCH + c8) * 2;
        const size_t gi = ((size_t)((kc << 7) + row) << 8) + c8;
        CP_ASYNC16(dst + doff, g_ch + gi);
        CP_ASYNC16(dst + SB_HL + doff, g_cl + gi);
    }
}

__global__ __launch_bounds__(512, 1) void gemm_argmin() {
    extern __shared__ char sm[];
    __nv_bfloat16* Ah = (__nv_bfloat16*)(sm + SA);
    float* c2s = (float*)(sm + S_C2);
    float* x2s = (float*)(sm + S_X2);
    float* mgv = (float*)(sm + S_MGV);
    int*   mgi = (int*)(sm + S_MGI);

    const int t    = threadIdx.x;
    const int lane = t & 31;
    const int w    = t >> 5;                      // 0..15
    const int wm   = (w >> 2) << 5;               // M base row: 0,32,64,96
    const int wq   = w & 3;                       // N quarter of 128-chunk
    const int n0   = blockIdx.x * 128;
    const int g = lane >> 2, q = lane & 3;
    const uint32_t sb = smem_u32(sm);

    // resident A (hi), c2, x2
#pragma unroll
    for (int i = 0; i < 8; ++i) {
        const int e = t + (i << 9);
        const int row = e >> 5, c8 = (e & 31) << 3;
        *(uint4*)(Ah + row * PITCH + c8) =
            *(const uint4*)(g_xh + ((size_t)(n0 + row) << 8) + c8);
    }
#pragma unroll
    for (int i = 0; i < 2; ++i) c2s[t + (i << 9)] = g_c2[t + (i << 9)];
    if (t < 128) x2s[t] = g_x2[n0 + t];

    const uint32_t a_idx = (uint32_t)((wm + (lane & 15)) * PITCH + ((lane >> 4) << 3));
    const uint32_t aoh = sb + SA + a_idx * 2;
    const uint32_t b_idx = (uint32_t)(((lane & 7) + ((lane >> 4) << 3)) * PITCH
                                      + (((lane >> 3) & 1) << 3));
    const uint32_t bgrp = (uint32_t)((wq << 5) * PITCH) * 2;   // N-quarter offset

    float tv[4][4];
    int   ti[4][4];
#pragma unroll
    for (int r = 0; r < 4; ++r)
#pragma unroll
        for (int s = 0; s < 4; ++s) { tv[r][s] = FINF; ti[r][s] = 0; }

    for (int nc = 0; nc < 8; ++nc) {
        __syncthreads();                          // prev chunk consumed
        stage_b(sb, nc, t);
        CP_COMMIT();
        CP_WAIT(0);
        __syncthreads();

        const uint32_t bh = sb + SB + bgrp + b_idx * 2;
        const uint32_t bl = bh + SB_HL;

        float acc[2][4][4];
#pragma unroll
        for (int mh = 0; mh < 2; ++mh)
#pragma unroll
            for (int j = 0; j < 4; ++j)
#pragma unroll
                for (int s = 0; s < 4; ++s) acc[mh][j][s] = 0.f;

#pragma unroll 2
        for (int k = 0; k < 16; ++k) {
            uint32_t a00, a01, a02, a03, a10, a11, a12, a13;
            uint32_t h00, h01, h02, h03, h10, h11, h12, h13;
            uint32_t l00, l01, l02, l03, l10, l11, l12, l13;
            LDSM_X4(a00, a01, a02, a03, aoh + k * 32);
            LDSM_X4(a10, a11, a12, a13, aoh + 16 * PITCH * 2 + k * 32);
            LDSM_X4(h00, h01, h02, h03, bh + k * 32);
            LDSM_X4(h10, h11, h12, h13, bh + 16 * PITCH * 2 + k * 32);
            LDSM_X4(l00, l01, l02, l03, bl + k * 32);
            LDSM_X4(l10, l11, l12, l13, bl + 16 * PITCH * 2 + k * 32);
            // pass hh
            MMA_BF16(acc[0][0], a00, a01, a02, a03, h00, h01);
            MMA_BF16(acc[0][1], a00, a01, a02, a03, h02, h03);
            MMA_BF16(acc[0][2], a00, a01, a02, a03, h10, h11);
            MMA_BF16(acc[0][3], a00, a01, a02, a03, h12, h13);
            MMA_BF16(acc[1][0], a10, a11, a12, a13, h00, h01);
            MMA_BF16(acc[1][1], a10, a11, a12, a13, h02, h03);
            MMA_BF16(acc[1][2], a10, a11, a12, a13, h10, h11);
            MMA_BF16(acc[1][3], a10, a11, a12, a13, h12, h13);
            // pass hl
            MMA_BF16(acc[0][0], a00, a01, a02, a03, l00, l01);
            MMA_BF16(acc[0][1], a00, a01, a02, a03, l02, l03);
            MMA_BF16(acc[0][2], a00, a01, a02, a03, l10, l11);
            MMA_BF16(acc[0][3], a00, a01, a02, a03, l12, l13);
            MMA_BF16(acc[1][0], a10, a11, a12, a13, l00, l01);
            MMA_BF16(acc[1][1], a10, a11, a12, a13, l02, l03);
            MMA_BF16(acc[1][2], a10, a11, a12, a13, l10, l11);
            MMA_BF16(acc[1][3], a10, a11, a12, a13, l12, l13);
        }

        // epilogue: fold this warp's 32x32 tile into 4 per-thread top-4 lists
#pragma unroll
        for (int mh = 0; mh < 2; ++mh) {
            const float x2a = x2s[wm + (mh << 4) + g];
            const float x2b = x2s[wm + (mh << 4) + 8 + g];
#pragma unroll
            for (int j = 0; j < 4; ++j) {
                const int colb = (nc << 7) + (wq << 5) + (j << 3) + (q << 1);
                const float c2a = c2s[colb], c2b = c2s[colb + 1];
                fold4(tv[mh * 2],     ti[mh * 2],
                      __fadd_rn(__fadd_rn(x2a, -2.f * acc[mh][j][0]), c2a), colb);
                fold4(tv[mh * 2],     ti[mh * 2],
                      __fadd_rn(__fadd_rn(x2a, -2.f * acc[mh][j][1]), c2b), colb + 1);
                fold4(tv[mh * 2 + 1], ti[mh * 2 + 1],
                      __fadd_rn(__fadd_rn(x2b, -2.f * acc[mh][j][2]), c2a), colb);
                fold4(tv[mh * 2 + 1], ti[mh * 2 + 1],
                      __fadd_rn(__fadd_rn(x2b, -2.f * acc[mh][j][3]), c2b), colb + 1);
            }
        }
    }

    // merge across the 4 q-lanes via shuffles
#pragma unroll
    for (int r = 0; r < 4; ++r) {
#pragma unroll
        for (int m = 1; m <= 2; m <<= 1) {
            float ov[4]; int oi[4];
#pragma unroll
            for (int s = 0; s < 4; ++s) {
                ov[s] = __shfl_xor_sync(0xffffffffu, tv[r][s], m);
                oi[s] = __shfl_xor_sync(0xffffffffu, ti[r][s], m);
            }
#pragma unroll
            for (int s = 0; s < 4; ++s) fold4(tv[r], ti[r], ov[s], oi[s]);
        }
    }
    __syncthreads();
    if (q == 0) {
#pragma unroll
        for (int r = 0; r < 4; ++r) {
            const int row = wm + ((r & 1) << 3) + ((r >> 1) << 4) + g;
#pragma unroll
            for (int s = 0; s < 4; ++s) {
                mgv[(row * 4 + wq) * 4 + s] = tv[r][s];
                mgi[(row * 4 + wq) * 4 + s] = ti[r][s];
            }
        }
    }
    __syncthreads();
    if (t < 128) {
        float bv[4] = {FINF, FINF, FINF, FINF};
        int   bi[4] = {0, 0, 0, 0};
#pragma unroll
        for (int qq = 0; qq < 4; ++qq)
#pragma unroll
            for (int s = 0; s < 4; ++s)
                fold4(bv, bi, mgv[(t * 4 + qq) * 4 + s], mgi[(t * 4 + qq) * 4 + s]);
        const int n = n0 + t;
#pragma unroll
        for (int s = 0; s < 4; ++s) { g_cv[n][s] = bv[s]; g_ci[n][s] = bi[s]; }
    }
}

// ---------------------------------------------------------------------------
// classify: resolve unambiguous rows; compact the rest into work queues.
// ---------------------------------------------------------------------------
__global__ __launch_bounds__(256) void classify_kernel() {
    const int n = blockIdx.x * 256 + threadIdx.x;
    const float lim = g_cv[n][0] + MARGIN;
    const int ncand = 1 + (g_cv[n][1] <= lim) + (g_cv[n][2] <= lim)
                        + (g_cv[n][3] <= lim);
    if (ncand == 1) {
        g_idx[n] = g_ci[n][0];
    } else if (ncand < 4) {
        g_qa[atomicAdd(&g_qa_n, 1)] = n;
    } else {
        g_qb[atomicAdd(&g_qb_n, 1)] = n;
    }
}

// ---------------------------------------------------------------------------
// refine_small: persistent warps grid-stride over queue A (2-3 candidates).
// ---------------------------------------------------------------------------
__global__ __launch_bounds__(256) void refine_small(const float* __restrict__ cb)
{
    __shared__ float sx[8][260];
    __shared__ float sc[8][3][260];
    const int w = threadIdx.x >> 5;
    const int l = threadIdx.x & 31;
    const int wi = (blockIdx.x << 3) + w;
    const int stride = gridDim.x << 3;
    const int cnt = g_qa_n;

    for (int i = wi; i < cnt; i += stride) {
        const int n = g_qa[i];
        const float lim = g_cv[n][0] + MARGIN;
        const int ncand = 2 + (g_cv[n][2] <= lim);

        {
            const float* xr = g_xt + ((size_t)n << 8);
#pragma unroll
            for (int ii = 0; ii < 2; ++ii) {
                const int d = (l + (ii << 5)) << 2;
                *(float4*)&sx[w][d] = *(const float4*)(xr + d);
            }
        }
        for (int c = 0; c < ncand; ++c) {
            const float* cr = cb + ((size_t)g_ci[n][c] << 8);
#pragma unroll
            for (int ii = 0; ii < 2; ++ii) {
                const int d = (l + (ii << 5)) << 2;
                *(float4*)&sc[w][c][d] = *(const float4*)(cr + d);
            }
        }
        __syncwarp();

        float bestv = FINF;
        int   besti = 0x7fffffff;
        if (l < ncand) {
            const int k = g_ci[n][l];
            float s = 0.f;
#pragma unroll 16
            for (int d = 0; d < D_; ++d)
                s = fmaf(sx[w][d], sc[w][l][d], s);
            bestv = __fadd_rn(__fadd_rn(g_x2[n], -2.f * s), g_c2[k]);
            besti = k;
        }
#pragma unroll
        for (int m = 16; m; m >>= 1) {
            const float ov = __shfl_xor_sync(0xffffffffu, bestv, m);
            const int   oi = __shfl_xor_sync(0xffffffffu, besti, m);
            if (ov < bestv || (ov == bestv && oi < besti)) { bestv = ov; besti = oi; }
        }
        if (l == 0) g_idx[n] = besti;
        __syncwarp();
    }
}

// ---------------------------------------------------------------------------
// refine_full (batched): 8 saturated rows per block share each staged
// 64-code chunk. Exact chains, first-min tie-break. dyn smem: 64*257 floats.
// ---------------------------------------------------------------------------
__global__ __launch_bounds__(256) void refine_full(const float* __restrict__ cb)
{
    extern __shared__ float scf[];          // [64][257]
    __shared__ float sx[8][260];
    __shared__ float x2s[8];
    __shared__ int   rown[8];
    __shared__ float c2s[K_];
    __shared__ float bvS[8][64];
    __shared__ int   biS[8][64];
    const int t = threadIdx.x;
    const int cnt = g_qb_n;
    const int c = t & 63, r = t >> 6;

#pragma unroll
    for (int i = 0; i < 4; ++i) c2s[t + (i << 8)] = g_c2[t + (i << 8)];

    for (int q0 = blockIdx.x * 8; q0 < cnt; q0 += gridDim.x * 8) {
        const int nrows = min(8, cnt - q0);
        __syncthreads();
        if (t < 8 && t < nrows) {
            const int n = g_qb[q0 + t];
            rown[t] = n;
            x2s[t] = g_x2[n];
        }
#pragma unroll
        for (int i = 0; i < 2; ++i) {
            const int slot = t + (i << 8);
            const int rr = slot >> 6, d4 = (slot & 63) << 2;
            if (rr < nrows) {
                const int n = g_qb[q0 + rr];
                *(float4*)&sx[rr][d4] = *(const float4*)(g_xt + ((size_t)n << 8) + d4);
            }
        }

        float bv0 = FINF, bv1 = FINF;
        int   bi0 = 0x7fffffff, bi1 = 0x7fffffff;

        for (int nc = 0; nc < 16; ++nc) {
            __syncthreads();
#pragma unroll
            for (int i = 0; i < 16; ++i) {
                const int e = t + (i << 8);
                const int row = e >> 6, c4 = (e & 63) << 2;
                const float4 v = *(const float4*)(cb + ((size_t)((nc << 6) + row) << 8) + c4);
                float* dst = scf + row * 257 + c4;
                dst[0] = v.x; dst[1] = v.y; dst[2] = v.z; dst[3] = v.w;
            }
            __syncthreads();
            const int k = (nc << 6) + c;
            const float* cr = scf + c * 257;
            float s0 = 0.f, s1 = 0.f;
#pragma unroll 8
            for (int d = 0; d < D_; ++d) {
                const float cv = cr[d];
                s0 = fmaf(sx[r][d],     cv, s0);
                s1 = fmaf(sx[r + 4][d], cv, s1);
            }
            const float v0 = __fadd_rn(__fadd_rn(x2s[r],     -2.f * s0), c2s[k]);
            const float v1 = __fadd_rn(__fadd_rn(x2s[r + 4], -2.f * s1), c2s[k]);
            if (v0 < bv0) { bv0 = v0; bi0 = k; }
            if (v1 < bv1) { bv1 = v1; bi1 = k; }
        }

        bvS[r][c] = bv0;     biS[r][c] = bi0;
        bvS[r + 4][c] = bv1; biS[r + 4][c] = bi1;
        __syncthreads();

        const int w = t >> 5, l = t & 31;
        if (w < nrows) {
            float v = bvS[w][l];        int kk = biS[w][l];
            const float v2 = bvS[w][l + 32]; const int k2 = biS[w][l + 32];
            if (v2 < v || (v2 == v && k2 < kk)) { v = v2; kk = k2; }
#pragma unroll
            for (int m = 16; m; m >>= 1) {
                const float ov = __shfl_xor_sync(0xffffffffu, v, m);
                const int   oi = __shfl_xor_sync(0xffffffffu, kk, m);
                if (ov < v || (ov == v && oi < kk)) { v = ov; kk = oi; }
            }
            if (l == 0) g_idx[rown[w]] = kk;
        }
    }
}

// ---------------------------------------------------------------------------
// quant v2: gathered codebook rows staged to smem (coalesced; conflict-free
// pitch-257 reads), straight-through output + loss partials + idx-as-float.
// dyn smem: 64*257 floats.
// ---------------------------------------------------------------------------
__global__ __launch_bounds__(256) void quant_kernel(
    const float* __restrict__ x, const float* __restrict__ cb,
    float* __restrict__ out, long long out_size)
{
    extern __shared__ float sc[];           // [64][257]
    __shared__ float red[256];
    __shared__ int   ks[64];
    const int t   = threadIdx.x;
    const int n0  = blockIdx.x * 64;
    const int b   = n0 / HW_;
    const int hw0 = n0 % HW_;
    const int tn  = t & 63;
    const int dz  = t >> 6;
    const int n   = n0 + tn;

    if (t < 64) ks[t] = g_idx[n0 + t];
    __syncthreads();

    // stage 64 gathered codebook rows (coalesced within each row)
#pragma unroll
    for (int i = 0; i < 16; ++i) {
        const int e = t + (i << 8);
        const int row = e >> 6, f4 = (e & 63) << 2;
        const float4 v = *(const float4*)(cb + ((size_t)ks[row] << 8) + f4);
        float* dst = sc + row * 257 + f4;
        dst[0] = v.x; dst[1] = v.y; dst[2] = v.z; dst[3] = v.w;
    }
    __syncthreads();

    const float* xb = x   + (size_t)b * D_ * HW_ + hw0 + tn;
    float*       ob = out + (size_t)b * D_ * HW_ + hw0 + tn;
    const float* cr = sc + tn * 257;

    float s = 0.f;
#pragma unroll 8
    for (int d = dz; d < D_; d += 4) {
        const float xv   = xb[(size_t)d * HW_];
        const float cv   = cr[d];
        const float diff = __fadd_rn(cv, -xv);
        ob[(size_t)d * HW_] = __fadd_rn(xv, diff);
        s = fmaf(diff, diff, s);
    }

    if (dz == 0 && out_size >= Q_OFF + 3 + N_)
        out[Q_OFF + 3 + n] = (float)ks[tn];

    red[t] = s;
    __syncthreads();
    for (int w = 128; w > 0; w >>= 1) {
        if (t < w) red[t] += red[t + w];
        __syncthreads();
    }
    if (t == 0) atomicAdd(&g_acc, (double)red[0]);
}

__global__ void finalize_kernel(float* __restrict__ out, long long out_size) {
    if (out_size >= Q_OFF + 3) {
        const double m = g_acc / (double)((long long)N_ * D_);
        const float  l = (float)m;
        out[Q_OFF + 0] = l;
        out[Q_OFF + 1] = l;
        out[Q_OFF + 2] = __fadd_rn(l, 0.25f * l);
    }
}

// ---------------------------------------------------------------------------
extern "C" void kernel_launch(void* const* d_in, const int* in_sizes, int n_in,
                              void* d_out, int out_size)
{
    const float* x  = (const float*)d_in[0];
    const float* cb = (const float*)d_in[1];
    float*       out = (float*)d_out;
    const long long osz = (long long)out_size;

    cudaFuncSetAttribute(prep_x,
        cudaFuncAttributeMaxDynamicSharedMemorySize, 64 * 257 * 4);
    cudaFuncSetAttribute(gemm_argmin,
        cudaFuncAttributeMaxDynamicSharedMemorySize, GEMM_SMEM);
    cudaFuncSetAttribute(refine_full,
        cudaFuncAttributeMaxDynamicSharedMemorySize, 64 * 257 * 4);
    cudaFuncSetAttribute(quant_kernel,
        cudaFuncAttributeMaxDynamicSharedMemorySize, 64 * 257 * 4);

    zero_kernel<<<1, 1>>>();                       // launch 1
    prep_cb<<<K_, 256>>>(cb);                      // launch 2
    prep_x<<<512, 256, 64 * 257 * 4>>>(x);         // launch 3
    gemm_argmin<<<N_ / 128, 512, GEMM_SMEM>>>();   // launch 4 (ncu target)
    classify_kernel<<<N_ / 256, 256>>>();          // launch 5
    refine_small<<<256, 256>>>(cb);                // launch 6
    refine_full<<<64, 256, 64 * 257 * 4>>>(cb);    // launch 7
    quant_kernel<<<N_ / 64, 256, 64 * 257 * 4>>>(x, cb, out, osz);
    finalize_kernel<<<1, 1>>>(out, osz);
}

// round 13
// speedup vs baseline: 2.1991x; 1.2231x over previous
#include <cuda_runtime.h>
#include <cuda_bf16.h>
#include <cstdint>

#define B_   32
#define D_   256
#define HW_  1024
#define N_   32768
#define K_   1024
#define MARGIN 3e-4f
#define FINF 3.4e38f

static const long long Q_OFF = 8388608LL;   // B*D*H*W

// ---------------- device globals ----------------
__device__ int    g_idx[N_];
__device__ float  g_c2[K_];
__device__ float  g_x2[N_];
__device__ double g_acc;
__device__ __align__(16) float         g_xt[(size_t)N_ * D_];
__device__ __align__(16) __nv_bfloat16 g_xh[(size_t)N_ * D_];
__device__ __align__(16) __nv_bfloat16 g_ch[(size_t)K_ * D_];
__device__ float g_cv[N_][4];
__device__ int   g_ci[N_][4];
__device__ int   g_qa[N_];
__device__ int   g_qb[N_];
__device__ int   g_qa_n;
__device__ int   g_qb_n;

__device__ __forceinline__ uint32_t smem_u32(const void* p) {
    uint32_t a;
    asm("{ .reg .u64 t; cvta.to.shared.u64 t, %1; cvt.u32.u64 %0, t; }"
        : "=r"(a) : "l"(p));
    return a;
}
#define LDSM_X4(r0, r1, r2, r3, addr) \
    asm volatile("ldmatrix.sync.aligned.m8n8.x4.shared.b16 {%0,%1,%2,%3}, [%4];" \
                 : "=r"(r0), "=r"(r1), "=r"(r2), "=r"(r3) : "r"(addr))
#define MMA_BF16(c, a0, a1, a2, a3, b0, b1) \
    asm volatile("mma.sync.aligned.m16n8k16.row.col.f32.bf16.bf16.f32 " \
                 "{%0,%1,%2,%3}, {%4,%5,%6,%7}, {%8,%9}, {%0,%1,%2,%3};" \
                 : "+f"((c)[0]), "+f"((c)[1]), "+f"((c)[2]), "+f"((c)[3]) \
                 : "r"(a0), "r"(a1), "r"(a2), "r"(a3), "r"(b0), "r"(b1))
#define CP_ASYNC16(dst, src) \
    asm volatile("cp.async.cg.shared.global [%0], [%1], 16;" \
                 :: "r"(dst), "l"(src))
#define CP_COMMIT() asm volatile("cp.async.commit_group;" ::: "memory")
#define CP_WAIT(n)  asm volatile("cp.async.wait_group %0;" :: "n"(n) : "memory")

__device__ __forceinline__ void fold4(float* v, int* ix, float nv, int nk) {
    if (nv < v[3]) {
        if (nv < v[2]) {
            v[3] = v[2]; ix[3] = ix[2];
            if (nv < v[1]) {
                v[2] = v[1]; ix[2] = ix[1];
                if (nv < v[0]) { v[1] = v[0]; ix[1] = ix[0]; v[0] = nv; ix[0] = nk; }
                else           { v[1] = nv; ix[1] = nk; }
            } else { v[2] = nv; ix[2] = nk; }
        } else { v[3] = nv; ix[3] = nk; }
    }
}

// ---------------------------------------------------------------------------
__global__ void zero_kernel() { g_acc = 0.0; g_qa_n = 0; g_qb_n = 0; }

// ---------------------------------------------------------------------------
// prep_cb: bf16 hi split; exact c2 (sequential no-FMA).
// ---------------------------------------------------------------------------
__global__ __launch_bounds__(256) void prep_cb(const float* __restrict__ cb) {
    __shared__ float row[256];
    const int k = blockIdx.x, t = threadIdx.x;
    const float v = cb[(size_t)k * D_ + t];
    row[t] = v;
    g_ch[(size_t)k * D_ + t] = __float2bfloat16(v);
    __syncthreads();
    if (t == 0) {
        float s = 0.f;
        for (int d = 0; d < D_; ++d)
            s = __fadd_rn(s, __fmul_rn(row[d], row[d]));
        g_c2[k] = s;
    }
}

// ---------------------------------------------------------------------------
// prep_x: float4 transpose loads, x2 chain on warps 0-1 (others bypass),
// packed float2/bf16x2 writes. dyn smem: 64*257 floats.
// ---------------------------------------------------------------------------
__global__ __launch_bounds__(256) void prep_x(const float* __restrict__ x) {
    extern __shared__ float xs[];   // [64 n][257 d]
    const int t   = threadIdx.x;
    const int n0  = blockIdx.x * 64;
    const int b   = n0 >> 10;
    const int hw0 = n0 & 1023;
    const float* xb = x + ((size_t)b << 18) + hw0;

#pragma unroll
    for (int i = 0; i < 16; ++i) {
        const int e  = t + (i << 8);
        const int d  = e >> 4;
        const int n4 = (e & 15) << 2;
        const float4 v = *(const float4*)(xb + ((size_t)d << 10) + n4);
        xs[(n4 + 0) * 257 + d] = v.x;
        xs[(n4 + 1) * 257 + d] = v.y;
        xs[(n4 + 2) * 257 + d] = v.z;
        xs[(n4 + 3) * 257 + d] = v.w;
    }
    __syncthreads();

    if (t < 64) {
        const float* r = xs + t * 257;
        float s = 0.f;
        for (int d = 0; d < D_; ++d)
            s = __fadd_rn(s, __fmul_rn(r[d], r[d]));
        g_x2[n0 + t] = s;
    }

#pragma unroll
    for (int i = 0; i < 32; ++i) {
        const int e  = t + (i << 8);
        const int n  = e >> 7;
        const int d2 = (e & 127) << 1;
        const float v0 = xs[n * 257 + d2];
        const float v1 = xs[n * 257 + d2 + 1];
        const size_t gi = ((size_t)(n0 + n) << 8) + d2;
        *(float2*)(g_xt + gi) = make_float2(v0, v1);
        __nv_bfloat162 hp;
        hp.x = __float2bfloat16(v0);
        hp.y = __float2bfloat16(v1);
        *(__nv_bfloat162*)(g_xh + gi) = hp;
    }
}

// ---------------------------------------------------------------------------
// gemm_argmin: SINGLE-pass HMMA (s = xh*ch; noise sigma ~1.4e-5, margin
// 3e-4 = 10.7 sigma; exact refine repairs all in-margin rows — validated
// rel_err 0.0 in R9). 128-row CTA, 512 threads = 16 warps (4 M x 4 N),
// 128-code B-hi chunks cp.async double-buffered. Fused top-4 epilogue.
// ---------------------------------------------------------------------------
#define PITCH 264
#define SA        0
#define SB        (128 * PITCH * 2)               // 67584
#define SB_STRIDE (128 * PITCH * 2)               // 67584 per buffer
#define S_C2      (SB + 2 * SB_STRIDE)            // 202752
#define S_X2      (S_C2 + 4096)                   // 206848
#define S_MGV     (S_X2 + 512)                    // 207360 (128*4*4 floats)
#define S_MGI     (S_MGV + 8192)                  // 215552
#define GEMM_SMEM (S_MGI + 8192)                  // 223744

__device__ __forceinline__ void stage_b(uint32_t sb, int buf, int kc, int t) {
    const uint32_t dst = sb + SB + buf * SB_STRIDE;
#pragma unroll
    for (int i = 0; i < 8; ++i) {
        const int e = t + (i << 9);               // 0..4095
        const int row = e >> 5;                   // 0..127
        const int c8 = (e & 31) << 3;             // 0..248
        CP_ASYNC16(dst + (uint32_t)(row * PITCH + c8) * 2,
                   g_ch + (((size_t)((kc << 7) + row)) << 8) + c8);
    }
}

__global__ __launch_bounds__(512, 1) void gemm_argmin() {
    extern __shared__ char sm[];
    __nv_bfloat16* Ah = (__nv_bfloat16*)(sm + SA);
    float* c2s = (float*)(sm + S_C2);
    float* x2s = (float*)(sm + S_X2);
    float* mgv = (float*)(sm + S_MGV);
    int*   mgi = (int*)(sm + S_MGI);

    const int t    = threadIdx.x;
    const int lane = t & 31;
    const int w    = t >> 5;                      // 0..15
    const int wm   = (w >> 2) << 5;               // M base row: 0,32,64,96
    const int wq   = w & 3;                       // N quarter of 128-chunk
    const int n0   = blockIdx.x * 128;
    const int g = lane >> 2, q = lane & 3;
    const uint32_t sb = smem_u32(sm);

    stage_b(sb, 0, 0, t);
    CP_COMMIT();

    // resident A (hi), c2, x2
#pragma unroll
    for (int i = 0; i < 8; ++i) {
        const int e = t + (i << 9);
        const int row = e >> 5, c8 = (e & 31) << 3;
        *(uint4*)(Ah + row * PITCH + c8) =
            *(const uint4*)(g_xh + ((size_t)(n0 + row) << 8) + c8);
    }
#pragma unroll
    for (int i = 0; i < 2; ++i) c2s[t + (i << 9)] = g_c2[t + (i << 9)];
    if (t < 128) x2s[t] = g_x2[n0 + t];

    const uint32_t a_idx = (uint32_t)((wm + (lane & 15)) * PITCH + ((lane >> 4) << 3));
    const uint32_t aoh = sb + SA + a_idx * 2;
    const uint32_t b_idx = (uint32_t)(((lane & 7) + ((lane >> 4) << 3)) * PITCH
                                      + (((lane >> 3) & 1) << 3));
    const uint32_t bgrp = (uint32_t)((wq << 5) * PITCH) * 2;   // N-quarter offset

    float tv[4][4];
    int   ti[4][4];
#pragma unroll
    for (int r = 0; r < 4; ++r)
#pragma unroll
        for (int s = 0; s < 4; ++s) { tv[r][s] = FINF; ti[r][s] = 0; }

    for (int nc = 0; nc < 8; ++nc) {
        const int buf = nc & 1;
        if (nc < 7) { stage_b(sb, buf ^ 1, nc + 1, t); CP_COMMIT(); CP_WAIT(1); }
        else        { CP_WAIT(0); }
        __syncthreads();

        const uint32_t bh = sb + SB + buf * SB_STRIDE + bgrp + b_idx * 2;

        float acc[2][4][4];
#pragma unroll
        for (int mh = 0; mh < 2; ++mh)
#pragma unroll
            for (int j = 0; j < 4; ++j)
#pragma unroll
                for (int s = 0; s < 4; ++s) acc[mh][j][s] = 0.f;

#pragma unroll 4
        for (int k = 0; k < 16; ++k) {
            uint32_t a00, a01, a02, a03, a10, a11, a12, a13;
            uint32_t h00, h01, h02, h03, h10, h11, h12, h13;
            LDSM_X4(a00, a01, a02, a03, aoh + k * 32);
            LDSM_X4(a10, a11, a12, a13, aoh + 16 * PITCH * 2 + k * 32);
            LDSM_X4(h00, h01, h02, h03, bh + k * 32);
            LDSM_X4(h10, h11, h12, h13, bh + 16 * PITCH * 2 + k * 32);
            MMA_BF16(acc[0][0], a00, a01, a02, a03, h00, h01);
            MMA_BF16(acc[0][1], a00, a01, a02, a03, h02, h03);
            MMA_BF16(acc[0][2], a00, a01, a02, a03, h10, h11);
            MMA_BF16(acc[0][3], a00, a01, a02, a03, h12, h13);
            MMA_BF16(acc[1][0], a10, a11, a12, a13, h00, h01);
            MMA_BF16(acc[1][1], a10, a11, a12, a13, h02, h03);
            MMA_BF16(acc[1][2], a10, a11, a12, a13, h10, h11);
            MMA_BF16(acc[1][3], a10, a11, a12, a13, h12, h13);
        }

        // epilogue: fold this warp's 32x32 tile into 4 per-thread top-4 lists
#pragma unroll
        for (int mh = 0; mh < 2; ++mh) {
            const float x2a = x2s[wm + (mh << 4) + g];
            const float x2b = x2s[wm + (mh << 4) + 8 + g];
#pragma unroll
            for (int j = 0; j < 4; ++j) {
                const int colb = (nc << 7) + (wq << 5) + (j << 3) + (q << 1);
                const float c2a = c2s[colb], c2b = c2s[colb + 1];
                fold4(tv[mh * 2],     ti[mh * 2],
                      __fadd_rn(__fadd_rn(x2a, -2.f * acc[mh][j][0]), c2a), colb);
                fold4(tv[mh * 2],     ti[mh * 2],
                      __fadd_rn(__fadd_rn(x2a, -2.f * acc[mh][j][1]), c2b), colb + 1);
                fold4(tv[mh * 2 + 1], ti[mh * 2 + 1],
                      __fadd_rn(__fadd_rn(x2b, -2.f * acc[mh][j][2]), c2a), colb);
                fold4(tv[mh * 2 + 1], ti[mh * 2 + 1],
                      __fadd_rn(__fadd_rn(x2b, -2.f * acc[mh][j][3]), c2b), colb + 1);
            }
        }
        __syncthreads();        // buf fully consumed before it is re-staged
    }

    // merge across the 4 q-lanes via shuffles
#pragma unroll
    for (int r = 0; r < 4; ++r) {
#pragma unroll
        for (int m = 1; m <= 2; m <<= 1) {
            float ov[4]; int oi[4];
#pragma unroll
            for (int s = 0; s < 4; ++s) {
                ov[s] = __shfl_xor_sync(0xffffffffu, tv[r][s], m);
                oi[s] = __shfl_xor_sync(0xffffffffu, ti[r][s], m);
            }
#pragma unroll
            for (int s = 0; s < 4; ++s) fold4(tv[r], ti[r], ov[s], oi[s]);
        }
    }
    if (q == 0) {
#pragma unroll
        for (int r = 0; r < 4; ++r) {
            const int row = wm + ((r & 1) << 3) + ((r >> 1) << 4) + g;
#pragma unroll
            for (int s = 0; s < 4; ++s) {
                mgv[(row * 4 + wq) * 4 + s] = tv[r][s];
                mgi[(row * 4 + wq) * 4 + s] = ti[r][s];
            }
        }
    }
    __syncthreads();
    if (t < 128) {
        float bv[4] = {FINF, FINF, FINF, FINF};
        int   bi[4] = {0, 0, 0, 0};
#pragma unroll
        for (int qq = 0; qq < 4; ++qq)
#pragma unroll
            for (int s = 0; s < 4; ++s)
                fold4(bv, bi, mgv[(t * 4 + qq) * 4 + s], mgi[(t * 4 + qq) * 4 + s]);
        const int n = n0 + t;
#pragma unroll
        for (int s = 0; s < 4; ++s) { g_cv[n][s] = bv[s]; g_ci[n][s] = bi[s]; }
    }
}

// ---------------------------------------------------------------------------
// classify: resolve unambiguous rows; compact the rest into work queues.
// ---------------------------------------------------------------------------
__global__ __launch_bounds__(256) void classify_kernel() {
    const int n = blockIdx.x * 256 + threadIdx.x;
    const float lim = g_cv[n][0] + MARGIN;
    const int ncand = 1 + (g_cv[n][1] <= lim) + (g_cv[n][2] <= lim)
                        + (g_cv[n][3] <= lim);
    if (ncand == 1) {
        g_idx[n] = g_ci[n][0];
    } else if (ncand < 4) {
        g_qa[atomicAdd(&g_qa_n, 1)] = n;
    } else {
        g_qb[atomicAdd(&g_qb_n, 1)] = n;
    }
}

// ---------------------------------------------------------------------------
// refine_small: persistent warps grid-stride over queue A (2-3 candidates).
// ---------------------------------------------------------------------------
__global__ __launch_bounds__(256) void refine_small(const float* __restrict__ cb)
{
    __shared__ float sx[8][260];
    __shared__ float sc[8][3][260];
    const int w = threadIdx.x >> 5;
    const int l = threadIdx.x & 31;
    const int wi = (blockIdx.x << 3) + w;
    const int stride = gridDim.x << 3;
    const int cnt = g_qa_n;

    for (int i = wi; i < cnt; i += stride) {
        const int n = g_qa[i];
        const float lim = g_cv[n][0] + MARGIN;
        const int ncand = 2 + (g_cv[n][2] <= lim);

        {
            const float* xr = g_xt + ((size_t)n << 8);
#pragma unroll
            for (int ii = 0; ii < 2; ++ii) {
                const int d = (l + (ii << 5)) << 2;
                *(float4*)&sx[w][d] = *(const float4*)(xr + d);
            }
        }
        for (int c = 0; c < ncand; ++c) {
            const float* cr = cb + ((size_t)g_ci[n][c] << 8);
#pragma unroll
            for (int ii = 0; ii < 2; ++ii) {
                const int d = (l + (ii << 5)) << 2;
                *(float4*)&sc[w][c][d] = *(const float4*)(cr + d);
            }
        }
        __syncwarp();

        float bestv = FINF;
        int   besti = 0x7fffffff;
        if (l < ncand) {
            const int k = g_ci[n][l];
            float s = 0.f;
#pragma unroll 16
            for (int d = 0; d < D_; ++d)
                s = fmaf(sx[w][d], sc[w][l][d], s);
            bestv = __fadd_rn(__fadd_rn(g_x2[n], -2.f * s), g_c2[k]);
            besti = k;
        }
#pragma unroll
        for (int m = 16; m; m >>= 1) {
            const float ov = __shfl_xor_sync(0xffffffffu, bestv, m);
            const int   oi = __shfl_xor_sync(0xffffffffu, besti, m);
            if (ov < bestv || (ov == bestv && oi < besti)) { bestv = ov; besti = oi; }
        }
        if (l == 0) g_idx[n] = besti;
        __syncwarp();
    }
}

// ---------------------------------------------------------------------------
// refine_full (batched): 8 saturated rows per block share each staged
// 64-code chunk. Exact chains, first-min tie-break. dyn smem: 64*257 floats.
// ---------------------------------------------------------------------------
__global__ __launch_bounds__(256) void refine_full(const float* __restrict__ cb)
{
    extern __shared__ float scf[];          // [64][257]
    __shared__ float sx[8][260];
    __shared__ float x2s[8];
    __shared__ int   rown[8];
    __shared__ float c2s[K_];
    __shared__ float bvS[8][64];
    __shared__ int   biS[8][64];
    const int t = threadIdx.x;
    const int cnt = g_qb_n;
    const int c = t & 63, r = t >> 6;

#pragma unroll
    for (int i = 0; i < 4; ++i) c2s[t + (i << 8)] = g_c2[t + (i << 8)];

    for (int q0 = blockIdx.x * 8; q0 < cnt; q0 += gridDim.x * 8) {
        const int nrows = min(8, cnt - q0);
        __syncthreads();
        if (t < 8 && t < nrows) {
            const int n = g_qb[q0 + t];
            rown[t] = n;
            x2s[t] = g_x2[n];
        }
#pragma unroll
        for (int i = 0; i < 2; ++i) {
            const int slot = t + (i << 8);
            const int rr = slot >> 6, d4 = (slot & 63) << 2;
            if (rr < nrows) {
                const int n = g_qb[q0 + rr];
                *(float4*)&sx[rr][d4] = *(const float4*)(g_xt + ((size_t)n << 8) + d4);
            }
        }

        float bv0 = FINF, bv1 = FINF;
        int   bi0 = 0x7fffffff, bi1 = 0x7fffffff;

        for (int nc = 0; nc < 16; ++nc) {
            __syncthreads();
#pragma unroll
            for (int i = 0; i < 16; ++i) {
                const int e = t + (i << 8);
                const int row = e >> 6, c4 = (e & 63) << 2;
                const float4 v = *(const float4*)(cb + ((size_t)((nc << 6) + row) << 8) + c4);
                float* dst = scf + row * 257 + c4;
                dst[0] = v.x; dst[1] = v.y; dst[2] = v.z; dst[3] = v.w;
            }
            __syncthreads();
            const int k = (nc << 6) + c;
            const float* cr = scf + c * 257;
            float s0 = 0.f, s1 = 0.f;
#pragma unroll 8
            for (int d = 0; d < D_; ++d) {
                const float cv = cr[d];
                s0 = fmaf(sx[r][d],     cv, s0);
                s1 = fmaf(sx[r + 4][d], cv, s1);
            }
            const float v0 = __fadd_rn(__fadd_rn(x2s[r],     -2.f * s0), c2s[k]);
            const float v1 = __fadd_rn(__fadd_rn(x2s[r + 4], -2.f * s1), c2s[k]);
            if (v0 < bv0) { bv0 = v0; bi0 = k; }
            if (v1 < bv1) { bv1 = v1; bi1 = k; }
        }

        bvS[r][c] = bv0;     biS[r][c] = bi0;
        bvS[r + 4][c] = bv1; biS[r + 4][c] = bi1;
        __syncthreads();

        const int w = t >> 5, l = t & 31;
        if (w < nrows) {
            float v = bvS[w][l];        int kk = biS[w][l];
            const float v2 = bvS[w][l + 32]; const int k2 = biS[w][l + 32];
            if (v2 < v || (v2 == v && k2 < kk)) { v = v2; kk = k2; }
#pragma unroll
            for (int m = 16; m; m >>= 1) {
                const float ov = __shfl_xor_sync(0xffffffffu, v, m);
                const int   oi = __shfl_xor_sync(0xffffffffu, kk, m);
                if (ov < v || (ov == v && oi < kk)) { v = ov; kk = oi; }
            }
            if (l == 0) g_idx[rown[w]] = kk;
        }
    }
}

// ---------------------------------------------------------------------------
// quant: gathered codebook rows staged to smem, straight-through output +
// loss partials + idx-as-float. dyn smem: 64*257 floats.
// ---------------------------------------------------------------------------
__global__ __launch_bounds__(256) void quant_kernel(
    const float* __restrict__ x, const float* __restrict__ cb,
    float* __restrict__ out, long long out_size)
{
    extern __shared__ float sc[];           // [64][257]
    __shared__ float red[256];
    __shared__ int   ks[64];
    const int t   = threadIdx.x;
    const int n0  = blockIdx.x * 64;
    const int b   = n0 / HW_;
    const int hw0 = n0 % HW_;
    const int tn  = t & 63;
    const int dz  = t >> 6;
    const int n   = n0 + tn;

    if (t < 64) ks[t] = g_idx[n0 + t];
    __syncthreads();

#pragma unroll
    for (int i = 0; i < 16; ++i) {
        const int e = t + (i << 8);
        const int row = e >> 6, f4 = (e & 63) << 2;
        const float4 v = *(const float4*)(cb + ((size_t)ks[row] << 8) + f4);
        float* dst = sc + row * 257 + f4;
        dst[0] = v.x; dst[1] = v.y; dst[2] = v.z; dst[3] = v.w;
    }
    __syncthreads();

    const float* xb = x   + (size_t)b * D_ * HW_ + hw0 + tn;
    float*       ob = out + (size_t)b * D_ * HW_ + hw0 + tn;
    const float* cr = sc + tn * 257;

    float s = 0.f;
#pragma unroll 8
    for (int d = dz; d < D_; d += 4) {
        const float xv   = xb[(size_t)d * HW_];
        const float cv   = cr[d];
        const float diff = __fadd_rn(cv, -xv);
        ob[(size_t)d * HW_] = __fadd_rn(xv, diff);
        s = fmaf(diff, diff, s);
    }

    if (dz == 0 && out_size >= Q_OFF + 3 + N_)
        out[Q_OFF + 3 + n] = (float)ks[tn];

    red[t] = s;
    __syncthreads();
    for (int w = 128; w > 0; w >>= 1) {
        if (t < w) red[t] += red[t + w];
        __syncthreads();
    }
    if (t == 0) atomicAdd(&g_acc, (double)red[0]);
}

__global__ void finalize_kernel(float* __restrict__ out, long long out_size) {
    if (out_size >= Q_OFF + 3) {
        const double m = g_acc / (double)((long long)N_ * D_);
        const float  l = (float)m;
        out[Q_OFF + 0] = l;
        out[Q_OFF + 1] = l;
        out[Q_OFF + 2] = __fadd_rn(l, 0.25f * l);
    }
}

// ---------------------------------------------------------------------------
extern "C" void kernel_launch(void* const* d_in, const int* in_sizes, int n_in,
                              void* d_out, int out_size)
{
    const float* x  = (const float*)d_in[0];
    const float* cb = (const float*)d_in[1];
    float*       out = (float*)d_out;
    const long long osz = (long long)out_size;

    cudaFuncSetAttribute(prep_x,
        cudaFuncAttributeMaxDynamicSharedMemorySize, 64 * 257 * 4);
    cudaFuncSetAttribute(gemm_argmin,
        cudaFuncAttributeMaxDynamicSharedMemorySize, GEMM_SMEM);
    cudaFuncSetAttribute(refine_full,
        cudaFuncAttributeMaxDynamicSharedMemorySize, 64 * 257 * 4);
    cudaFuncSetAttribute(quant_kernel,
        cudaFuncAttributeMaxDynamicSharedMemorySize, 64 * 257 * 4);

    zero_kernel<<<1, 1>>>();                       // launch 1
    prep_cb<<<K_, 256>>>(cb);                      // launch 2
    prep_x<<<512, 256, 64 * 257 * 4>>>(x);         // launch 3
    gemm_argmin<<<N_ / 128, 512, GEMM_SMEM>>>();   // launch 4 (ncu target)
    classify_kernel<<<N_ / 256, 256>>>();          // launch 5
    refine_small<<<256, 256>>>(cb);                // launch 6
    refine_full<<<64, 256, 64 * 257 * 4>>>(cb);    // launch 7
    quant_kernel<<<N_ / 64, 256, 64 * 257 * 4>>>(x, cb, out, osz);
    finalize_kernel<<<1, 1>>>(out, osz);
}

// round 14
// speedup vs baseline: 2.2227x; 1.0107x over previous
#include <cuda_runtime.h>
#include <cuda_bf16.h>
#include <cstdint>

#define B_   32
#define D_   256
#define HW_  1024
#define N_   32768
#define K_   1024
#define MARGIN 3e-4f
#define FINF 3.4e38f

static const long long Q_OFF = 8388608LL;   // B*D*H*W

// ---------------- device globals ----------------
__device__ int    g_idx[N_];
__device__ float  g_c2[K_];
__device__ float  g_x2[N_];
__device__ double g_acc;
__device__ __align__(16) float         g_xt[(size_t)N_ * D_];
__device__ __align__(16) __nv_bfloat16 g_xh[(size_t)N_ * D_];
__device__ __align__(16) __nv_bfloat16 g_ch[(size_t)K_ * D_];
__device__ float g_cv[N_][4];   // NOTE: stores (c2 - 2s) — x2 dropped (row-constant)
__device__ int   g_ci[N_][4];
__device__ int   g_qa[N_];
__device__ int   g_qb[N_];
__device__ int   g_qa_n;
__device__ int   g_qb_n;

__device__ __forceinline__ uint32_t smem_u32(const void* p) {
    uint32_t a;
    asm("{ .reg .u64 t; cvta.to.shared.u64 t, %1; cvt.u32.u64 %0, t; }"
        : "=r"(a) : "l"(p));
    return a;
}
#define LDSM_X4(r0, r1, r2, r3, addr) \
    asm volatile("ldmatrix.sync.aligned.m8n8.x4.shared.b16 {%0,%1,%2,%3}, [%4];" \
                 : "=r"(r0), "=r"(r1), "=r"(r2), "=r"(r3) : "r"(addr))
#define MMA_BF16(c, a0, a1, a2, a3, b0, b1) \
    asm volatile("mma.sync.aligned.m16n8k16.row.col.f32.bf16.bf16.f32 " \
                 "{%0,%1,%2,%3}, {%4,%5,%6,%7}, {%8,%9}, {%0,%1,%2,%3};" \
                 : "+f"((c)[0]), "+f"((c)[1]), "+f"((c)[2]), "+f"((c)[3]) \
                 : "r"(a0), "r"(a1), "r"(a2), "r"(a3), "r"(b0), "r"(b1))
#define CP_ASYNC16(dst, src) \
    asm volatile("cp.async.cg.shared.global [%0], [%1], 16;" \
                 :: "r"(dst), "l"(src))
#define CP_COMMIT() asm volatile("cp.async.commit_group;" ::: "memory")
#define CP_WAIT(n)  asm volatile("cp.async.wait_group %0;" :: "n"(n) : "memory")

__device__ __forceinline__ void fold4(float* v, int* ix, float nv, int nk) {
    if (nv < v[3]) {
        if (nv < v[2]) {
            v[3] = v[2]; ix[3] = ix[2];
            if (nv < v[1]) {
                v[2] = v[1]; ix[2] = ix[1];
                if (nv < v[0]) { v[1] = v[0]; ix[1] = ix[0]; v[0] = nv; ix[0] = nk; }
                else           { v[1] = nv; ix[1] = nk; }
            } else { v[2] = nv; ix[2] = nk; }
        } else { v[3] = nv; ix[3] = nk; }
    }
}

// ---------------------------------------------------------------------------
__global__ void zero_kernel() { g_acc = 0.0; g_qa_n = 0; g_qb_n = 0; }

// ---------------------------------------------------------------------------
// prep_cb: bf16 hi split; exact c2 (sequential no-FMA).
// ---------------------------------------------------------------------------
__global__ __launch_bounds__(256) void prep_cb(const float* __restrict__ cb) {
    __shared__ float row[256];
    const int k = blockIdx.x, t = threadIdx.x;
    const float v = cb[(size_t)k * D_ + t];
    row[t] = v;
    g_ch[(size_t)k * D_ + t] = __float2bfloat16(v);
    __syncthreads();
    if (t == 0) {
        float s = 0.f;
        for (int d = 0; d < D_; ++d)
            s = __fadd_rn(s, __fmul_rn(row[d], row[d]));
        g_c2[k] = s;
    }
}

// ---------------------------------------------------------------------------
// prep_x: float4 transpose loads, x2 chain on warps 0-1 (others bypass),
// packed float2/bf16x2 writes. dyn smem: 64*257 floats.
// ---------------------------------------------------------------------------
__global__ __launch_bounds__(256) void prep_x(const float* __restrict__ x) {
    extern __shared__ float xs[];   // [64 n][257 d]
    const int t   = threadIdx.x;
    const int n0  = blockIdx.x * 64;
    const int b   = n0 >> 10;
    const int hw0 = n0 & 1023;
    const float* xb = x + ((size_t)b << 18) + hw0;

#pragma unroll
    for (int i = 0; i < 16; ++i) {
        const int e  = t + (i << 8);
        const int d  = e >> 4;
        const int n4 = (e & 15) << 2;
        const float4 v = *(const float4*)(xb + ((size_t)d << 10) + n4);
        xs[(n4 + 0) * 257 + d] = v.x;
        xs[(n4 + 1) * 257 + d] = v.y;
        xs[(n4 + 2) * 257 + d] = v.z;
        xs[(n4 + 3) * 257 + d] = v.w;
    }
    __syncthreads();

    if (t < 64) {
        const float* r = xs + t * 257;
        float s = 0.f;
        for (int d = 0; d < D_; ++d)
            s = __fadd_rn(s, __fmul_rn(r[d], r[d]));
        g_x2[n0 + t] = s;
    }

#pragma unroll
    for (int i = 0; i < 32; ++i) {
        const int e  = t + (i << 8);
        const int n  = e >> 7;
        const int d2 = (e & 127) << 1;
        const float v0 = xs[n * 257 + d2];
        const float v1 = xs[n * 257 + d2 + 1];
        const size_t gi = ((size_t)(n0 + n) << 8) + d2;
        *(float2*)(g_xt + gi) = make_float2(v0, v1);
        __nv_bfloat162 hp;
        hp.x = __float2bfloat16(v0);
        hp.y = __float2bfloat16(v1);
        *(__nv_bfloat162*)(g_xh + gi) = hp;
    }
}

// ---------------------------------------------------------------------------
// gemm_argmin: single-pass HMMA (s = xh*ch), x2-free epilogue:
//   v = fmaf(-2, s, c2)   (x2 is row-constant -> argmin/margins unchanged)
// 128-row CTA, 512 threads = 16 warps (4M x 4N), 128-code B chunks
// cp.async double-buffered. Fused top-4 epilogue.
// ---------------------------------------------------------------------------
#define PITCH 264
#define SA        0
#define SB        (128 * PITCH * 2)               // 67584
#define SB_STRIDE (128 * PITCH * 2)               // 67584 per buffer
#define S_C2      (SB + 2 * SB_STRIDE)            // 202752
#define S_MGV     (S_C2 + 4096)                   // 206848 (128*4*4 floats)
#define S_MGI     (S_MGV + 8192)                  // 215040
#define GEMM_SMEM (S_MGI + 8192)                  // 223232

__device__ __forceinline__ void stage_b(uint32_t sb, int buf, int kc, int t) {
    const uint32_t dst = sb + SB + buf * SB_STRIDE;
#pragma unroll
    for (int i = 0; i < 8; ++i) {
        const int e = t + (i << 9);               // 0..4095
        const int row = e >> 5;                   // 0..127
        const int c8 = (e & 31) << 3;             // 0..248
        CP_ASYNC16(dst + (uint32_t)(row * PITCH + c8) * 2,
                   g_ch + (((size_t)((kc << 7) + row)) << 8) + c8);
    }
}

__global__ __launch_bounds__(512, 1) void gemm_argmin() {
    extern __shared__ char sm[];
    __nv_bfloat16* Ah = (__nv_bfloat16*)(sm + SA);
    float* c2s = (float*)(sm + S_C2);
    float* mgv = (float*)(sm + S_MGV);
    int*   mgi = (int*)(sm + S_MGI);

    const int t    = threadIdx.x;
    const int lane = t & 31;
    const int w    = t >> 5;                      // 0..15
    const int wm   = (w >> 2) << 5;               // M base row: 0,32,64,96
    const int wq   = w & 3;                       // N quarter of 128-chunk
    const int n0   = blockIdx.x * 128;
    const int g = lane >> 2, q = lane & 3;
    const uint32_t sb = smem_u32(sm);

    stage_b(sb, 0, 0, t);
    CP_COMMIT();

    // resident A (hi), c2
#pragma unroll
    for (int i = 0; i < 8; ++i) {
        const int e = t + (i << 9);
        const int row = e >> 5, c8 = (e & 31) << 3;
        *(uint4*)(Ah + row * PITCH + c8) =
            *(const uint4*)(g_xh + ((size_t)(n0 + row) << 8) + c8);
    }
#pragma unroll
    for (int i = 0; i < 2; ++i) c2s[t + (i << 9)] = g_c2[t + (i << 9)];

    const uint32_t a_idx = (uint32_t)((wm + (lane & 15)) * PITCH + ((lane >> 4) << 3));
    const uint32_t aoh = sb + SA + a_idx * 2;
    const uint32_t b_idx = (uint32_t)(((lane & 7) + ((lane >> 4) << 3)) * PITCH
                                      + (((lane >> 3) & 1) << 3));
    const uint32_t bgrp = (uint32_t)((wq << 5) * PITCH) * 2;   // N-quarter offset
    const int col_off = (wq << 5) + (q << 1);     // warp-lane column base

    float tv[4][4];
    int   ti[4][4];
#pragma unroll
    for (int r = 0; r < 4; ++r)
#pragma unroll
        for (int s = 0; s < 4; ++s) { tv[r][s] = FINF; ti[r][s] = 0; }

    for (int nc = 0; nc < 8; ++nc) {
        const int buf = nc & 1;
        if (nc < 7) { stage_b(sb, buf ^ 1, nc + 1, t); CP_COMMIT(); CP_WAIT(1); }
        else        { CP_WAIT(0); }
        __syncthreads();

        const uint32_t bh = sb + SB + buf * SB_STRIDE + bgrp + b_idx * 2;

        float acc[2][4][4];
#pragma unroll
        for (int mh = 0; mh < 2; ++mh)
#pragma unroll
            for (int j = 0; j < 4; ++j)
#pragma unroll
                for (int s = 0; s < 4; ++s) acc[mh][j][s] = 0.f;

#pragma unroll 8
        for (int k = 0; k < 16; ++k) {
            uint32_t a00, a01, a02, a03, a10, a11, a12, a13;
            uint32_t h00, h01, h02, h03, h10, h11, h12, h13;
            LDSM_X4(a00, a01, a02, a03, aoh + k * 32);
            LDSM_X4(a10, a11, a12, a13, aoh + 16 * PITCH * 2 + k * 32);
            LDSM_X4(h00, h01, h02, h03, bh + k * 32);
            LDSM_X4(h10, h11, h12, h13, bh + 16 * PITCH * 2 + k * 32);
            MMA_BF16(acc[0][0], a00, a01, a02, a03, h00, h01);
            MMA_BF16(acc[0][1], a00, a01, a02, a03, h02, h03);
            MMA_BF16(acc[0][2], a00, a01, a02, a03, h10, h11);
            MMA_BF16(acc[0][3], a00, a01, a02, a03, h12, h13);
            MMA_BF16(acc[1][0], a10, a11, a12, a13, h00, h01);
            MMA_BF16(acc[1][1], a10, a11, a12, a13, h02, h03);
            MMA_BF16(acc[1][2], a10, a11, a12, a13, h10, h11);
            MMA_BF16(acc[1][3], a10, a11, a12, a13, h12, h13);
        }

        // epilogue: v = fmaf(-2, s, c2) (x2 dropped: row-constant shift)
        const int colb0 = (nc << 7) + col_off;
#pragma unroll
        for (int j = 0; j < 4; ++j) {
            const int   colb = colb0 + (j << 3);
            const float c2a = c2s[colb], c2b = c2s[colb + 1];
#pragma unroll
            for (int mh = 0; mh < 2; ++mh) {
                fold4(tv[mh * 2],     ti[mh * 2],
                      fmaf(-2.f, acc[mh][j][0], c2a), colb);
                fold4(tv[mh * 2],     ti[mh * 2],
                      fmaf(-2.f, acc[mh][j][1], c2b), colb + 1);
                fold4(tv[mh * 2 + 1], ti[mh * 2 + 1],
                      fmaf(-2.f, acc[mh][j][2], c2a), colb);
                fold4(tv[mh * 2 + 1], ti[mh * 2 + 1],
                      fmaf(-2.f, acc[mh][j][3], c2b), colb + 1);
            }
        }
        __syncthreads();        // buf fully consumed before it is re-staged
    }

    // merge across the 4 q-lanes via shuffles
#pragma unroll
    for (int r = 0; r < 4; ++r) {
#pragma unroll
        for (int m = 1; m <= 2; m <<= 1) {
            float ov[4]; int oi[4];
#pragma unroll
            for (int s = 0; s < 4; ++s) {
                ov[s] = __shfl_xor_sync(0xffffffffu, tv[r][s], m);
                oi[s] = __shfl_xor_sync(0xffffffffu, ti[r][s], m);
            }
#pragma unroll
            for (int s = 0; s < 4; ++s) fold4(tv[r], ti[r], ov[s], oi[s]);
        }
    }
    if (q == 0) {
#pragma unroll
        for (int r = 0; r < 4; ++r) {
            const int row = wm + ((r & 1) << 3) + ((r >> 1) << 4) + g;
#pragma unroll
            for (int s = 0; s < 4; ++s) {
                mgv[(row * 4 + wq) * 4 + s] = tv[r][s];
                mgi[(row * 4 + wq) * 4 + s] = ti[r][s];
            }
        }
    }
    __syncthreads();
    if (t < 128) {
        float bv[4] = {FINF, FINF, FINF, FINF};
        int   bi[4] = {0, 0, 0, 0};
#pragma unroll
        for (int qq = 0; qq < 4; ++qq)
#pragma unroll
            for (int s = 0; s < 4; ++s)
                fold4(bv, bi, mgv[(t * 4 + qq) * 4 + s], mgi[(t * 4 + qq) * 4 + s]);
        const int n = n0 + t;
#pragma unroll
        for (int s = 0; s < 4; ++s) { g_cv[n][s] = bv[s]; g_ci[n][s] = bi[s]; }
    }
}

// ---------------------------------------------------------------------------
// classify: resolve unambiguous rows; compact the rest into work queues.
// (g_cv holds c2-2s; margins are row-relative so semantics unchanged.)
// ---------------------------------------------------------------------------
__global__ __launch_bounds__(256) void classify_kernel() {
    const int n = blockIdx.x * 256 + threadIdx.x;
    const float lim = g_cv[n][0] + MARGIN;
    const int ncand = 1 + (g_cv[n][1] <= lim) + (g_cv[n][2] <= lim)
                        + (g_cv[n][3] <= lim);
    if (ncand == 1) {
        g_idx[n] = g_ci[n][0];
    } else if (ncand < 4) {
        g_qa[atomicAdd(&g_qa_n, 1)] = n;
    } else {
        g_qb[atomicAdd(&g_qb_n, 1)] = n;
    }
}

// ---------------------------------------------------------------------------
// refine_small: persistent warps grid-stride over queue A (2-3 candidates).
// ---------------------------------------------------------------------------
__global__ __launch_bounds__(256) void refine_small(const float* __restrict__ cb)
{
    __shared__ float sx[8][260];
    __shared__ float sc[8][3][260];
    const int w = threadIdx.x >> 5;
    const int l = threadIdx.x & 31;
    const int wi = (blockIdx.x << 3) + w;
    const int stride = gridDim.x << 3;
    const int cnt = g_qa_n;

    for (int i = wi; i < cnt; i += stride) {
        const int n = g_qa[i];
        const float lim = g_cv[n][0] + MARGIN;
        const int ncand = 2 + (g_cv[n][2] <= lim);

        {
            const float* xr = g_xt + ((size_t)n << 8);
#pragma unroll
            for (int ii = 0; ii < 2; ++ii) {
                const int d = (l + (ii << 5)) << 2;
                *(float4*)&sx[w][d] = *(const float4*)(xr + d);
            }
        }
        for (int c = 0; c < ncand; ++c) {
            const float* cr = cb + ((size_t)g_ci[n][c] << 8);
#pragma unroll
            for (int ii = 0; ii < 2; ++ii) {
                const int d = (l + (ii << 5)) << 2;
                *(float4*)&sc[w][c][d] = *(const float4*)(cr + d);
            }
        }
        __syncwarp();

        float bestv = FINF;
        int   besti = 0x7fffffff;
        if (l < ncand) {
            const int k = g_ci[n][l];
            float s = 0.f;
#pragma unroll 16
            for (int d = 0; d < D_; ++d)
                s = fmaf(sx[w][d], sc[w][l][d], s);
            bestv = __fadd_rn(__fadd_rn(g_x2[n], -2.f * s), g_c2[k]);
            besti = k;
        }
#pragma unroll
        for (int m = 16; m; m >>= 1) {
            const float ov = __shfl_xor_sync(0xffffffffu, bestv, m);
            const int   oi = __shfl_xor_sync(0xffffffffu, besti, m);
            if (ov < bestv || (ov == bestv && oi < besti)) { bestv = ov; besti = oi; }
        }
        if (l == 0) g_idx[n] = besti;
        __syncwarp();
    }
}

// ---------------------------------------------------------------------------
// refine_full (batched): 8 saturated rows per block share each staged
// 64-code chunk. Exact chains, first-min tie-break. dyn smem: 64*257 floats.
// ---------------------------------------------------------------------------
__global__ __launch_bounds__(256) void refine_full(const float* __restrict__ cb)
{
    extern __shared__ float scf[];          // [64][257]
    __shared__ float sx[8][260];
    __shared__ float x2s[8];
    __shared__ int   rown[8];
    __shared__ float c2s[K_];
    __shared__ float bvS[8][64];
    __shared__ int   biS[8][64];
    const int t = threadIdx.x;
    const int cnt = g_qb_n;
    const int c = t & 63, r = t >> 6;

#pragma unroll
    for (int i = 0; i < 4; ++i) c2s[t + (i << 8)] = g_c2[t + (i << 8)];

    for (int q0 = blockIdx.x * 8; q0 < cnt; q0 += gridDim.x * 8) {
        const int nrows = min(8, cnt - q0);
        __syncthreads();
        if (t < 8 && t < nrows) {
            const int n = g_qb[q0 + t];
            rown[t] = n;
            x2s[t] = g_x2[n];
        }
#pragma unroll
        for (int i = 0; i < 2; ++i) {
            const int slot = t + (i << 8);
            const int rr = slot >> 6, d4 = (slot & 63) << 2;
            if (rr < nrows) {
                const int n = g_qb[q0 + rr];
                *(float4*)&sx[rr][d4] = *(const float4*)(g_xt + ((size_t)n << 8) + d4);
            }
        }

        float bv0 = FINF, bv1 = FINF;
        int   bi0 = 0x7fffffff, bi1 = 0x7fffffff;

        for (int nc = 0; nc < 16; ++nc) {
            __syncthreads();
#pragma unroll
            for (int i = 0; i < 16; ++i) {
                const int e = t + (i << 8);
                const int row = e >> 6, c4 = (e & 63) << 2;
                const float4 v = *(const float4*)(cb + ((size_t)((nc << 6) + row) << 8) + c4);
                float* dst = scf + row * 257 + c4;
                dst[0] = v.x; dst[1] = v.y; dst[2] = v.z; dst[3] = v.w;
            }
            __syncthreads();
            const int k = (nc << 6) + c;
            const float* cr = scf + c * 257;
            float s0 = 0.f, s1 = 0.f;
#pragma unroll 8
            for (int d = 0; d < D_; ++d) {
                const float cv = cr[d];
                s0 = fmaf(sx[r][d],     cv, s0);
                s1 = fmaf(sx[r + 4][d], cv, s1);
            }
            const float v0 = __fadd_rn(__fadd_rn(x2s[r],     -2.f * s0), c2s[k]);
            const float v1 = __fadd_rn(__fadd_rn(x2s[r + 4], -2.f * s1), c2s[k]);
            if (v0 < bv0) { bv0 = v0; bi0 = k; }
            if (v1 < bv1) { bv1 = v1; bi1 = k; }
        }

        bvS[r][c] = bv0;     biS[r][c] = bi0;
        bvS[r + 4][c] = bv1; biS[r + 4][c] = bi1;
        __syncthreads();

        const int w = t >> 5, l = t & 31;
        if (w < nrows) {
            float v = bvS[w][l];        int kk = biS[w][l];
            const float v2 = bvS[w][l + 32]; const int k2 = biS[w][l + 32];
            if (v2 < v || (v2 == v && k2 < kk)) { v = v2; kk = k2; }
#pragma unroll
            for (int m = 16; m; m >>= 1) {
                const float ov = __shfl_xor_sync(0xffffffffu, v, m);
                const int   oi = __shfl_xor_sync(0xffffffffu, kk, m);
                if (ov < v || (ov == v && oi < kk)) { v = ov; kk = oi; }
            }
            if (l == 0) g_idx[rown[w]] = kk;
        }
    }
}

// ---------------------------------------------------------------------------
// quant: gathered codebook rows staged to smem, straight-through output +
// loss partials + idx-as-float. dyn smem: 64*257 floats.
// ---------------------------------------------------------------------------
__global__ __launch_bounds__(256) void quant_kernel(
    const float* __restrict__ x, const float* __restrict__ cb,
    float* __restrict__ out, long long out_size)
{
    extern __shared__ float sc[];           // [64][257]
    __shared__ float red[256];
    __shared__ int   ks[64];
    const int t   = threadIdx.x;
    const int n0  = blockIdx.x * 64;
    const int b   = n0 / HW_;
    const int hw0 = n0 % HW_;
    const int tn  = t & 63;
    const int dz  = t >> 6;
    const int n   = n0 + tn;

    if (t < 64) ks[t] = g_idx[n0 + t];
    __syncthreads();

#pragma unroll
    for (int i = 0; i < 16; ++i) {
        const int e = t + (i << 8);
        const int row = e >> 6, f4 = (e & 63) << 2;
        const float4 v = *(const float4*)(cb + ((size_t)ks[row] << 8) + f4);
        float* dst = sc + row * 257 + f4;
        dst[0] = v.x; dst[1] = v.y; dst[2] = v.z; dst[3] = v.w;
    }
    __syncthreads();

    const float* xb = x   + (size_t)b * D_ * HW_ + hw0 + tn;
    float*       ob = out + (size_t)b * D_ * HW_ + hw0 + tn;
    const float* cr = sc + tn * 257;

    float s = 0.f;
#pragma unroll 8
    for (int d = dz; d < D_; d += 4) {
        const float xv   = xb[(size_t)d * HW_];
        const float cv   = cr[d];
        const float diff = __fadd_rn(cv, -xv);
        ob[(size_t)d * HW_] = __fadd_rn(xv, diff);
        s = fmaf(diff, diff, s);
    }

    if (dz == 0 && out_size >= Q_OFF + 3 + N_)
        out[Q_OFF + 3 + n] = (float)ks[tn];

    red[t] = s;
    __syncthreads();
    for (int w = 128; w > 0; w >>= 1) {
        if (t < w) red[t] += red[t + w];
        __syncthreads();
    }
    if (t == 0) atomicAdd(&g_acc, (double)red[0]);
}

__global__ void finalize_kernel(float* __restrict__ out, long long out_size) {
    if (out_size >= Q_OFF + 3) {
        const double m = g_acc / (double)((long long)N_ * D_);
        const float  l = (float)m;
        out[Q_OFF + 0] = l;
        out[Q_OFF + 1] = l;
        out[Q_OFF + 2] = __fadd_rn(l, 0.25f * l);
    }
}

// ---------------------------------------------------------------------------
extern "C" void kernel_launch(void* const* d_in, const int* in_sizes, int n_in,
                              void* d_out, int out_size)
{
    const float* x  = (const float*)d_in[0];
    const float* cb = (const float*)d_in[1];
    float*       out = (float*)d_out;
    const long long osz = (long long)out_size;

    cudaFuncSetAttribute(prep_x,
        cudaFuncAttributeMaxDynamicSharedMemorySize, 64 * 257 * 4);
    cudaFuncSetAttribute(gemm_argmin,
        cudaFuncAttributeMaxDynamicSharedMemorySize, GEMM_SMEM);
    cudaFuncSetAttribute(refine_full,
        cudaFuncAttributeMaxDynamicSharedMemorySize, 64 * 257 * 4);
    cudaFuncSetAttribute(quant_kernel,
        cudaFuncAttributeMaxDynamicSharedMemorySize, 64 * 257 * 4);

    zero_kernel<<<1, 1>>>();                       // launch 1
    prep_cb<<<K_, 256>>>(cb);                      // launch 2
    prep_x<<<512, 256, 64 * 257 * 4>>>(x);         // launch 3
    gemm_argmin<<<N_ / 128, 512, GEMM_SMEM>>>();   // launch 4 (ncu target)
    classify_kernel<<<N_ / 256, 256>>>();          // launch 5
    refine_small<<<256, 256>>>(cb);                // launch 6
    refine_full<<<64, 256, 64 * 257 * 4>>>(cb);    // launch 7
    quant_kernel<<<N_ / 64, 256, 64 * 257 * 4>>>(x, cb, out, osz);
    finalize_kernel<<<1, 1>>>(out, osz);
}